// round 6
// baseline (speedup 1.0000x reference)
#include <cuda_runtime.h>
#include <cstdint>

// Problem constants
#define N_NODES 50000
#define E_EDGES 300000
#define IN_F    128
#define HFEAT   64
#define AHEADS  4
#define R_REL   3
#define H_DIM   256
#define RH      768          // R_REL * H_DIM
#define RN      (R_REL * N_NODES)
#define RE      (R_REL * E_EDGES)

// ---------------- device scratch (static, no allocations) ----------------
__device__ float g_hw [(size_t)N_NODES * RH];   // h @ [wW0|wW1|wW2] + bias  (153.6 MB)
__device__ float g_agg[(size_t)N_NODES * RH];   // concat of per-relation aggregates (153.6 MB)
__device__ float g_sa[N_NODES];                 // a_n = h.(dW u)
__device__ float g_sb[N_NODES];                 // b_n = h.(dW v)
__device__ float g_pq[(size_t)RN * 8];          // per (r,node): p[0..3], q[0..3] (q incl qc+ab)
__device__ float g_du[IN_F];
__device__ float g_dv[IN_F];
__device__ float g_PQ[R_REL * IN_F * 8];        // [r][i][8]: P heads 0..3, Q heads 0..3
__device__ float g_pqc[R_REL * 8];              // bias constants for p (0..3) and q (4..7)
__device__ float g_Cs;                          // db.(u+v) + fb
__device__ int   g_cnt[RN];
__device__ int   g_off[RN + 1];
__device__ int   g_cur[RN];
__device__ int   g_elist[RE];

// ---------------- f32x2 / cp.async helpers ----------------
__device__ __forceinline__ uint64_t pk2(float lo, float hi)
{
    uint64_t r;
    asm("mov.b64 %0, {%1, %2};" : "=l"(r) : "f"(lo), "f"(hi));
    return r;
}
__device__ __forceinline__ void unpk2(float& lo, float& hi, uint64_t v)
{
    asm("mov.b64 {%0, %1}, %2;" : "=f"(lo), "=f"(hi) : "l"(v));
}
__device__ __forceinline__ void ffma2(uint64_t& d, uint64_t a, uint64_t b)
{
    asm("fma.rn.f32x2 %0, %1, %2, %0;" : "+l"(d) : "l"(a), "l"(b));
}
__device__ __forceinline__ void cp_async16(void* smem_ptr, const void* gptr)
{
    uint32_t sa = (uint32_t)__cvta_generic_to_shared(smem_ptr);
    asm volatile("cp.async.cg.shared.global [%0], [%1], 16;" :: "r"(sa), "l"(gptr));
}
__device__ __forceinline__ void cp_commit()
{
    asm volatile("cp.async.commit_group;");
}
template <int N>
__device__ __forceinline__ void cp_wait()
{
    asm volatile("cp.async.wait_group %0;" :: "n"(N));
}

// ---------------- kernel: tiny precompute of folded sign/attention params ----------------
__global__ void k_precompute(const float* __restrict__ dW, const float* __restrict__ db,
                             const float* __restrict__ fW, const float* __restrict__ fb,
                             const float* __restrict__ wW, const float* __restrict__ wb,
                             const float* __restrict__ aW, const float* __restrict__ ab)
{
    int i = threadIdx.x;            // 0..127
    if (i < IN_F) {
        float s1 = 0.f, s2 = 0.f;
        for (int j = 0; j < H_DIM; j++) {
            float u = fW[j] + fW[512 + j];
            float v = fW[256 + j] - fW[512 + j];
            float w = dW[i * H_DIM + j];
            s1 = fmaf(w, u, s1);
            s2 = fmaf(w, v, s2);
        }
        g_du[i] = s1;
        g_dv[i] = s2;
        for (int r = 0; r < R_REL; r++) {
            for (int hd = 0; hd < AHEADS; hd++) {
                float p = 0.f, q = 0.f;
                const float* wr = wW + (size_t)r * IN_F * H_DIM + (size_t)i * H_DIM + hd * HFEAT;
                const float* a1 = aW + r * 2 * HFEAT;
                const float* a2 = a1 + HFEAT;
                for (int k = 0; k < HFEAT; k++) {
                    p = fmaf(wr[k], a1[k], p);
                    q = fmaf(wr[k], a2[k], q);
                }
                g_PQ[r * (IN_F * 8) + i * 8 + hd]     = p;
                g_PQ[r * (IN_F * 8) + i * 8 + 4 + hd] = q;
            }
        }
    }
    if (i == 0) {
        float cs = fb[0];
        for (int j = 0; j < H_DIM; j++) {
            float u = fW[j] + fW[512 + j];
            float v = fW[256 + j] - fW[512 + j];
            cs = fmaf(db[j], u + v, cs);
        }
        g_Cs = cs;
        for (int r = 0; r < R_REL; r++) {
            for (int hd = 0; hd < AHEADS; hd++) {
                float pc = 0.f, qc = 0.f;
                const float* wr = wb + r * H_DIM + hd * HFEAT;
                const float* a1 = aW + r * 2 * HFEAT;
                const float* a2 = a1 + HFEAT;
                for (int k = 0; k < HFEAT; k++) {
                    pc = fmaf(wr[k], a1[k], pc);
                    qc = fmaf(wr[k], a2[k], qc);
                }
                g_pqc[r * 8 + hd]     = pc;
                g_pqc[r * 8 + 4 + hd] = qc + ab[r];
            }
        }
    }
}

// ---------------- kernel: per-node scalars (warp per node) ----------------
__global__ __launch_bounds__(128) void k_node_scalars(const float* __restrict__ h)
{
    int warp = threadIdx.x >> 5;
    int lane = threadIdx.x & 31;
    int node = blockIdx.x * 4 + warp;
    if (node >= N_NODES) return;

    float4 h4 = *(const float4*)(h + (size_t)node * IN_F + lane * 4);
    const float* hv = (const float*)&h4;

    float a = 0.f, b = 0.f;
    float pr[24];
#pragma unroll
    for (int j = 0; j < 24; j++) pr[j] = 0.f;

#pragma unroll
    for (int t = 0; t < 4; t++) {
        float x = hv[t];
        int idx = lane * 4 + t;
        a = fmaf(x, g_du[idx], a);
        b = fmaf(x, g_dv[idx], b);
#pragma unroll
        for (int r = 0; r < R_REL; r++) {
            const float4* pq4 = (const float4*)&g_PQ[r * (IN_F * 8) + idx * 8];
            float4 c0 = pq4[0], c1 = pq4[1];
            const float* c = (const float*)&c0;
            const float* d = (const float*)&c1;
#pragma unroll
            for (int j = 0; j < 4; j++) {
                pr[r * 8 + j]     = fmaf(x, c[j], pr[r * 8 + j]);
                pr[r * 8 + 4 + j] = fmaf(x, d[j], pr[r * 8 + 4 + j]);
            }
        }
    }
#pragma unroll
    for (int off = 16; off; off >>= 1) {
        a += __shfl_xor_sync(0xffffffffu, a, off);
        b += __shfl_xor_sync(0xffffffffu, b, off);
#pragma unroll
        for (int j = 0; j < 24; j++)
            pr[j] += __shfl_xor_sync(0xffffffffu, pr[j], off);
    }
    if (lane == 0) {
        g_sa[node] = a;
        g_sb[node] = b;
#pragma unroll
        for (int r = 0; r < R_REL; r++)
#pragma unroll
            for (int j = 0; j < 8; j++)
                g_pq[((size_t)r * N_NODES + node) * 8 + j] = pr[r * 8 + j] + g_pqc[r * 8 + j];
    }
}

// ---------------- GEMM: C = A@B + bias  (f32x2, cp.async double-buffered) ----------------
#define BM 128
#define BN 128
#define BK 16
__global__ __launch_bounds__(256) void k_gemm(const float* __restrict__ A,
                                              const float* __restrict__ B,
                                              const float* __restrict__ bias,
                                              float* __restrict__ C,
                                              int M, int Ncols, int K, int splitB)
{
    __shared__ float As[2][BK][BM];
    __shared__ float Bs[2][BK][BN];

    int tid = threadIdx.x;
    int bx = blockIdx.x, by = blockIdx.y;
    int tx = tid & 15, ty = tid >> 4;

    const float* Bp;
    int bn0, ldB;
    if (splitB) {
        int rblk = (bx * BN) / 256;
        Bp = B + (size_t)rblk * K * 256;
        bn0 = bx * BN - rblk * 256;
        ldB = 256;
    } else {
        Bp = B; bn0 = bx * BN; ldB = Ncols;
    }

    int arow0 = by * BM;
    int row0 = tid >> 2, c40 = tid & 3;   // A-stage: rows row0 / row0+64, 16B chunk c40
    int brow = tid >> 5;                  // B-stage: rows brow / brow+8
    int bcol = (tid & 31) * 4;

    uint64_t acc2[4][8];
#pragma unroll
    for (int p = 0; p < 4; p++)
#pragma unroll
        for (int j = 0; j < 8; j++) acc2[p][j] = 0ull;

    float4 aR0, aR1;
    // prologue: load k-slice 0
    {
        int gm0 = arow0 + row0, gm1 = gm0 + 64;
        aR0 = (gm0 < M) ? *(const float4*)(A + (size_t)gm0 * K + c40 * 4)
                        : make_float4(0.f, 0.f, 0.f, 0.f);
        aR1 = (gm1 < M) ? *(const float4*)(A + (size_t)gm1 * K + c40 * 4)
                        : make_float4(0.f, 0.f, 0.f, 0.f);
        cp_async16(&Bs[0][brow][bcol],     Bp + (size_t)brow * ldB + bn0 + bcol);
        cp_async16(&Bs[0][brow + 8][bcol], Bp + (size_t)(brow + 8) * ldB + bn0 + bcol);
        cp_commit();
        As[0][c40 * 4 + 0][row0] = aR0.x;
        As[0][c40 * 4 + 1][row0] = aR0.y;
        As[0][c40 * 4 + 2][row0] = aR0.z;
        As[0][c40 * 4 + 3][row0] = aR0.w;
        As[0][c40 * 4 + 0][row0 + 64] = aR1.x;
        As[0][c40 * 4 + 1][row0 + 64] = aR1.y;
        As[0][c40 * 4 + 2][row0 + 64] = aR1.z;
        As[0][c40 * 4 + 3][row0 + 64] = aR1.w;
    }

    int niter = K / BK;
    for (int i = 0; i < niter; i++) {
        int cur = i & 1, nxt = cur ^ 1;
        bool more = (i + 1 < niter);
        if (more) {
            int kk = (i + 1) * BK;
            int gm0 = arow0 + row0, gm1 = gm0 + 64;
            aR0 = (gm0 < M) ? *(const float4*)(A + (size_t)gm0 * K + kk + c40 * 4)
                            : make_float4(0.f, 0.f, 0.f, 0.f);
            aR1 = (gm1 < M) ? *(const float4*)(A + (size_t)gm1 * K + kk + c40 * 4)
                            : make_float4(0.f, 0.f, 0.f, 0.f);
            cp_async16(&Bs[nxt][brow][bcol],     Bp + (size_t)(kk + brow) * ldB + bn0 + bcol);
            cp_async16(&Bs[nxt][brow + 8][bcol], Bp + (size_t)(kk + brow + 8) * ldB + bn0 + bcol);
            cp_commit();
            cp_wait<1>();
        } else {
            cp_wait<0>();
        }
        __syncthreads();

#pragma unroll
        for (int k = 0; k < BK; k++) {
            float4 a0 = *(const float4*)&As[cur][k][ty * 8];
            float4 a1 = *(const float4*)&As[cur][k][ty * 8 + 4];
            uint64_t ap[4];
            ap[0] = pk2(a0.x, a0.y);
            ap[1] = pk2(a0.z, a0.w);
            ap[2] = pk2(a1.x, a1.y);
            ap[3] = pk2(a1.z, a1.w);

            float4 b0 = *(const float4*)&Bs[cur][k][tx * 8];
            float4 b1 = *(const float4*)&Bs[cur][k][tx * 8 + 4];
            float bv[8] = {b0.x, b0.y, b0.z, b0.w, b1.x, b1.y, b1.z, b1.w};
            uint64_t bp[8];
#pragma unroll
            for (int j = 0; j < 8; j++) bp[j] = pk2(bv[j], bv[j]);

#pragma unroll
            for (int p = 0; p < 4; p++)
#pragma unroll
                for (int j = 0; j < 8; j++)
                    ffma2(acc2[p][j], ap[p], bp[j]);
        }
        __syncthreads();

        if (more) {
            As[nxt][c40 * 4 + 0][row0] = aR0.x;
            As[nxt][c40 * 4 + 1][row0] = aR0.y;
            As[nxt][c40 * 4 + 2][row0] = aR0.z;
            As[nxt][c40 * 4 + 3][row0] = aR0.w;
            As[nxt][c40 * 4 + 0][row0 + 64] = aR1.x;
            As[nxt][c40 * 4 + 1][row0 + 64] = aR1.y;
            As[nxt][c40 * 4 + 2][row0 + 64] = aR1.z;
            As[nxt][c40 * 4 + 3][row0 + 64] = aR1.w;
        }
    }

    int col0 = bx * BN + tx * 8;
    float4 bs0 = *(const float4*)&bias[col0];
    float4 bs1 = *(const float4*)&bias[col0 + 4];
    const float* bb = (const float*)&bs0;
    const float* bb2 = (const float*)&bs1;
#pragma unroll
    for (int p = 0; p < 4; p++) {
        float r0[8], r1[8];
#pragma unroll
        for (int j = 0; j < 8; j++) unpk2(r0[j], r1[j], acc2[p][j]);
        int gm0 = arow0 + ty * 8 + 2 * p;
        if (gm0 < M) {
            float4 o0 = make_float4(r0[0] + bb[0], r0[1] + bb[1], r0[2] + bb[2], r0[3] + bb[3]);
            float4 o1 = make_float4(r0[4] + bb2[0], r0[5] + bb2[1], r0[6] + bb2[2], r0[7] + bb2[3]);
            *(float4*)(C + (size_t)gm0 * Ncols + col0)     = o0;
            *(float4*)(C + (size_t)gm0 * Ncols + col0 + 4) = o1;
        }
        int gm1 = gm0 + 1;
        if (gm1 < M) {
            float4 o0 = make_float4(r1[0] + bb[0], r1[1] + bb[1], r1[2] + bb[2], r1[3] + bb[3]);
            float4 o1 = make_float4(r1[4] + bb2[0], r1[5] + bb2[1], r1[6] + bb2[2], r1[7] + bb2[3]);
            *(float4*)(C + (size_t)gm1 * Ncols + col0)     = o0;
            *(float4*)(C + (size_t)gm1 * Ncols + col0 + 4) = o1;
        }
    }
}

// ---------------- CSR build ----------------
__global__ void k_zero()
{
    int i = blockIdx.x * blockDim.x + threadIdx.x;
    if (i < RN) g_cnt[i] = 0;
}

// grid (chunks, R_REL)
__global__ void k_hist(const int* __restrict__ dst)
{
    int i = blockIdx.x * blockDim.x + threadIdx.x;
    int r = blockIdx.y;
    if (i < E_EDGES)
        atomicAdd(&g_cnt[r * N_NODES + dst[(size_t)r * E_EDGES + i]], 1);
}

__global__ __launch_bounds__(1024) void k_scan()
{
    __shared__ int sm[1024];
    int tid = threadIdx.x;
    int carry = 0;
    for (int base = 0; base < RN; base += 1024) {
        int i = base + tid;
        int v = (i < RN) ? g_cnt[i] : 0;
        sm[tid] = v;
        __syncthreads();
#pragma unroll
        for (int off = 1; off < 1024; off <<= 1) {
            int t = (tid >= off) ? sm[tid - off] : 0;
            __syncthreads();
            sm[tid] += t;
            __syncthreads();
        }
        int excl = carry + sm[tid] - v;
        if (i < RN) { g_off[i] = excl; g_cur[i] = excl; }
        carry += sm[1023];
        __syncthreads();
    }
    if (tid == 0) g_off[RN] = carry;
}

__global__ void k_scatter(const int* __restrict__ dst)
{
    int i = blockIdx.x * blockDim.x + threadIdx.x;
    int r = blockIdx.y;
    if (i < E_EDGES) {
        int pos = atomicAdd(&g_cur[r * N_NODES + dst[(size_t)r * E_EDGES + i]], 1);
        g_elist[pos] = i;
    }
}

// ---------------- aggregation: warp per (relation, node), TWO-PASS softmax ----------------
__global__ __launch_bounds__(256) void k_agg(const int* __restrict__ src)
{
    int widx = (blockIdx.x * blockDim.x + threadIdx.x) >> 5;
    int lane = threadIdx.x & 31;
    if (widx >= RN) return;
    int r = widx / N_NODES;
    int n = widx - r * N_NODES;
    int start = g_off[widx], end = g_off[widx + 1];
    size_t obase = (size_t)n * RH + r * H_DIM;

    if (start == end) {
#pragma unroll
        for (int k = 0; k < 8; k++) g_agg[obase + lane + 32 * k] = 0.f;
        return;
    }

    float qv[4];
    {
        const float* qp = &g_pq[((size_t)r * N_NODES + n) * 8 + 4];
#pragma unroll
        for (int hh = 0; hh < 4; hh++) qv[hh] = qp[hh];
    }
    float b_n = g_sb[n] + g_Cs;
    const float* hwbase = g_hw + r * H_DIM;
    const int* srcR = src + (size_t)r * E_EDGES;
    const float* pqR = g_pq + (size_t)r * N_NODES * 8;

    // pass 1: max + denominator from scalars only
    float m[4], den[4];
#pragma unroll
    for (int hh = 0; hh < 4; hh++) m[hh] = -1e30f;

    for (int pos = start; pos < end; pos++) {
        int s = srcR[g_elist[pos]];
        float sc = g_sa[s] + b_n;
        float sgn = (float)((sc > 0.f) - (sc < 0.f));
        float4 pv = *(const float4*)&pqR[(size_t)s * 8];
        float pvv[4] = {pv.x, pv.y, pv.z, pv.w};
#pragma unroll
        for (int hh = 0; hh < 4; hh++) {
            float al = fmaf(sgn, pvv[hh], qv[hh]);
            al = (al > 0.f) ? al : 0.01f * al;
            m[hh] = fmaxf(m[hh], al);
        }
    }
#pragma unroll
    for (int hh = 0; hh < 4; hh++) den[hh] = 0.f;
    for (int pos = start; pos < end; pos++) {
        int s = srcR[g_elist[pos]];
        float sc = g_sa[s] + b_n;
        float sgn = (float)((sc > 0.f) - (sc < 0.f));
        float4 pv = *(const float4*)&pqR[(size_t)s * 8];
        float pvv[4] = {pv.x, pv.y, pv.z, pv.w};
#pragma unroll
        for (int hh = 0; hh < 4; hh++) {
            float al = fmaf(sgn, pvv[hh], qv[hh]);
            al = (al > 0.f) ? al : 0.01f * al;
            den[hh] += __expf(al - m[hh]);
        }
    }
    float inv[4];
#pragma unroll
    for (int hh = 0; hh < 4; hh++) inv[hh] = 1.f / den[hh];

    // pass 2: accumulate with final weights (loads independent across edges)
    float acc[8];
#pragma unroll
    for (int k = 0; k < 8; k++) acc[k] = 0.f;

    int s_cur = srcR[g_elist[start]];
    for (int pos = start; pos < end; pos++) {
        int s = s_cur;
        if (pos + 1 < end) s_cur = srcR[g_elist[pos + 1]];
        float sc = g_sa[s] + b_n;
        float sgn = (float)((sc > 0.f) - (sc < 0.f));
        float4 pv = *(const float4*)&pqR[(size_t)s * 8];
        float pvv[4] = {pv.x, pv.y, pv.z, pv.w};
        float w[4];
#pragma unroll
        for (int hh = 0; hh < 4; hh++) {
            float al = fmaf(sgn, pvv[hh], qv[hh]);
            al = (al > 0.f) ? al : 0.01f * al;
            w[hh] = __expf(al - m[hh]) * inv[hh] * sgn;
        }
        const float* row = hwbase + (size_t)s * RH;
#pragma unroll
        for (int k = 0; k < 8; k++)
            acc[k] = fmaf(w[k >> 1], row[lane + 32 * k], acc[k]);
    }
#pragma unroll
    for (int k = 0; k < 8; k++)
        g_agg[obase + lane + 32 * k] = acc[k];
}

// ---------------- launch ----------------
extern "C" void kernel_launch(void* const* d_in, const int* in_sizes, int n_in,
                              void* d_out, int out_size)
{
    const float* h    = (const float*)d_in[0];
    const float* dW   = (const float*)d_in[1];
    const float* db   = (const float*)d_in[2];
    const float* fW   = (const float*)d_in[3];
    const float* fb   = (const float*)d_in[4];
    const float* wW   = (const float*)d_in[5];
    const float* wb   = (const float*)d_in[6];
    const float* aW   = (const float*)d_in[7];
    const float* ab   = (const float*)d_in[8];
    const float* linW = (const float*)d_in[9];
    const float* linb = (const float*)d_in[10];
    const int*   src  = (const int*)d_in[11];
    const int*   dst  = (const int*)d_in[12];
    float* out = (float*)d_out;

    float *p_hw = nullptr, *p_agg = nullptr;
    cudaGetSymbolAddress((void**)&p_hw, g_hw);
    cudaGetSymbolAddress((void**)&p_agg, g_agg);

    k_precompute<<<1, 128>>>(dW, db, fW, fb, wW, wb, aW, ab);          // 1
    k_zero<<<(RN + 255) / 256, 256>>>();                               // 2
    k_node_scalars<<<N_NODES / 4, 128>>>(h);                           // 3
    k_gemm<<<dim3(RH / BN, (N_NODES + BM - 1) / BM), 256>>>(h, wW, wb, p_hw,
                                                            N_NODES, RH, IN_F, 1); // 4
    k_hist<<<dim3((E_EDGES + 255) / 256, R_REL), 256>>>(dst);          // 5
    k_scan<<<1, 1024>>>();                                             // 6
    k_scatter<<<dim3((E_EDGES + 255) / 256, R_REL), 256>>>(dst);       // 7
    k_agg<<<RN / 8, 256>>>(src);                                       // 8
    k_gemm<<<dim3(H_DIM / BN, (N_NODES + BM - 1) / BM), 256>>>(p_agg, linW, linb, out,
                                                               N_NODES, H_DIM, RH, 0); // 9
}

// round 7
// speedup vs baseline: 1.2221x; 1.2221x over previous
#include <cuda_runtime.h>
#include <cstdint>

// Problem constants
#define N_NODES 50000
#define E_EDGES 300000
#define IN_F    128
#define HFEAT   64
#define AHEADS  4
#define R_REL   3
#define H_DIM   256
#define RH      768          // R_REL * H_DIM
#define RN      (R_REL * N_NODES)
#define RE      (R_REL * E_EDGES)
#define NCHUNK  ((RN + 1023) / 1024)   // 147 scan chunks

// ---------------- device scratch (static, no allocations) ----------------
__device__ float g_hw [(size_t)N_NODES * RH];   // h @ [wW0|wW1|wW2] + bias  (153.6 MB)
__device__ float g_agg[(size_t)N_NODES * RH];   // concat of per-relation aggregates (153.6 MB)
__device__ float g_sa[N_NODES];                 // a_n = h.(dW u)
__device__ float g_sb[N_NODES];                 // b_n = h.(dW v)
__device__ float g_pq[(size_t)RN * 8];          // per (r,node): p[0..3], q[0..3] (q incl qc+ab)
__device__ float g_du[IN_F];
__device__ float g_dv[IN_F];
__device__ float g_PQ[R_REL * IN_F * 8];        // [r][i][8]: P heads 0..3, Q heads 0..3
__device__ float g_pqc[R_REL * 8];              // bias constants for p (0..3) and q (4..7)
__device__ float g_Cs;                          // db.(u+v) + fb
__device__ int   g_cnt[RN];
__device__ int   g_off[RN + 1];
__device__ int   g_cur[RN];
__device__ int   g_elist[RE];
__device__ int   g_pre[RN];                     // per-element block-local exclusive prefix
__device__ int   g_bsum[NCHUNK];
__device__ int   g_boff[NCHUNK];

// ---------------- f32x2 / cp.async helpers ----------------
__device__ __forceinline__ uint64_t pk2(float lo, float hi)
{
    uint64_t r;
    asm("mov.b64 %0, {%1, %2};" : "=l"(r) : "f"(lo), "f"(hi));
    return r;
}
__device__ __forceinline__ void unpk2(float& lo, float& hi, uint64_t v)
{
    asm("mov.b64 {%0, %1}, %2;" : "=f"(lo), "=f"(hi) : "l"(v));
}
__device__ __forceinline__ void ffma2(uint64_t& d, uint64_t a, uint64_t b)
{
    asm("fma.rn.f32x2 %0, %1, %2, %0;" : "+l"(d) : "l"(a), "l"(b));
}
__device__ __forceinline__ void cp_async16(void* smem_ptr, const void* gptr)
{
    uint32_t sa = (uint32_t)__cvta_generic_to_shared(smem_ptr);
    asm volatile("cp.async.cg.shared.global [%0], [%1], 16;" :: "r"(sa), "l"(gptr));
}
__device__ __forceinline__ void cp_commit()
{
    asm volatile("cp.async.commit_group;");
}
template <int N>
__device__ __forceinline__ void cp_wait()
{
    asm volatile("cp.async.wait_group %0;" :: "n"(N));
}

// ---------------- kernel: tiny precompute of folded sign/attention params ----------------
__global__ void k_precompute(const float* __restrict__ dW, const float* __restrict__ db,
                             const float* __restrict__ fW, const float* __restrict__ fb,
                             const float* __restrict__ wW, const float* __restrict__ wb,
                             const float* __restrict__ aW, const float* __restrict__ ab)
{
    int i = threadIdx.x;            // 0..127
    if (i < IN_F) {
        float s1 = 0.f, s2 = 0.f;
        for (int j = 0; j < H_DIM; j++) {
            float u = fW[j] + fW[512 + j];
            float v = fW[256 + j] - fW[512 + j];
            float w = dW[i * H_DIM + j];
            s1 = fmaf(w, u, s1);
            s2 = fmaf(w, v, s2);
        }
        g_du[i] = s1;
        g_dv[i] = s2;
        for (int r = 0; r < R_REL; r++) {
            for (int hd = 0; hd < AHEADS; hd++) {
                float p = 0.f, q = 0.f;
                const float* wr = wW + (size_t)r * IN_F * H_DIM + (size_t)i * H_DIM + hd * HFEAT;
                const float* a1 = aW + r * 2 * HFEAT;
                const float* a2 = a1 + HFEAT;
                for (int k = 0; k < HFEAT; k++) {
                    p = fmaf(wr[k], a1[k], p);
                    q = fmaf(wr[k], a2[k], q);
                }
                g_PQ[r * (IN_F * 8) + i * 8 + hd]     = p;
                g_PQ[r * (IN_F * 8) + i * 8 + 4 + hd] = q;
            }
        }
    }
    if (i == 0) {
        float cs = fb[0];
        for (int j = 0; j < H_DIM; j++) {
            float u = fW[j] + fW[512 + j];
            float v = fW[256 + j] - fW[512 + j];
            cs = fmaf(db[j], u + v, cs);
        }
        g_Cs = cs;
        for (int r = 0; r < R_REL; r++) {
            for (int hd = 0; hd < AHEADS; hd++) {
                float pc = 0.f, qc = 0.f;
                const float* wr = wb + r * H_DIM + hd * HFEAT;
                const float* a1 = aW + r * 2 * HFEAT;
                const float* a2 = a1 + HFEAT;
                for (int k = 0; k < HFEAT; k++) {
                    pc = fmaf(wr[k], a1[k], pc);
                    qc = fmaf(wr[k], a2[k], qc);
                }
                g_pqc[r * 8 + hd]     = pc;
                g_pqc[r * 8 + 4 + hd] = qc + ab[r];
            }
        }
    }
}

// ---------------- kernel: per-node scalars (warp per node) ----------------
__global__ __launch_bounds__(128) void k_node_scalars(const float* __restrict__ h)
{
    int warp = threadIdx.x >> 5;
    int lane = threadIdx.x & 31;
    int node = blockIdx.x * 4 + warp;
    if (node >= N_NODES) return;

    float4 h4 = *(const float4*)(h + (size_t)node * IN_F + lane * 4);
    const float* hv = (const float*)&h4;

    float a = 0.f, b = 0.f;
    float pr[24];
#pragma unroll
    for (int j = 0; j < 24; j++) pr[j] = 0.f;

#pragma unroll
    for (int t = 0; t < 4; t++) {
        float x = hv[t];
        int idx = lane * 4 + t;
        a = fmaf(x, g_du[idx], a);
        b = fmaf(x, g_dv[idx], b);
#pragma unroll
        for (int r = 0; r < R_REL; r++) {
            const float4* pq4 = (const float4*)&g_PQ[r * (IN_F * 8) + idx * 8];
            float4 c0 = pq4[0], c1 = pq4[1];
            const float* c = (const float*)&c0;
            const float* d = (const float*)&c1;
#pragma unroll
            for (int j = 0; j < 4; j++) {
                pr[r * 8 + j]     = fmaf(x, c[j], pr[r * 8 + j]);
                pr[r * 8 + 4 + j] = fmaf(x, d[j], pr[r * 8 + 4 + j]);
            }
        }
    }
#pragma unroll
    for (int off = 16; off; off >>= 1) {
        a += __shfl_xor_sync(0xffffffffu, a, off);
        b += __shfl_xor_sync(0xffffffffu, b, off);
#pragma unroll
        for (int j = 0; j < 24; j++)
            pr[j] += __shfl_xor_sync(0xffffffffu, pr[j], off);
    }
    if (lane == 0) {
        g_sa[node] = a;
        g_sb[node] = b;
#pragma unroll
        for (int r = 0; r < R_REL; r++)
#pragma unroll
            for (int j = 0; j < 8; j++)
                g_pq[((size_t)r * N_NODES + node) * 8 + j] = pr[r * 8 + j] + g_pqc[r * 8 + j];
    }
}

// ---------------- GEMM: C = A@B + bias  (f32x2, cp.async double-buffered) ----------------
#define BM 128
#define BN 128
#define BK 16
__global__ __launch_bounds__(256) void k_gemm(const float* __restrict__ A,
                                              const float* __restrict__ B,
                                              const float* __restrict__ bias,
                                              float* __restrict__ C,
                                              int M, int Ncols, int K, int splitB)
{
    __shared__ float As[2][BK][BM];
    __shared__ float Bs[2][BK][BN];

    int tid = threadIdx.x;
    int bx = blockIdx.x, by = blockIdx.y;
    int tx = tid & 15, ty = tid >> 4;

    const float* Bp;
    int bn0, ldB;
    if (splitB) {
        int rblk = (bx * BN) / 256;
        Bp = B + (size_t)rblk * K * 256;
        bn0 = bx * BN - rblk * 256;
        ldB = 256;
    } else {
        Bp = B; bn0 = bx * BN; ldB = Ncols;
    }

    int arow0 = by * BM;
    int row0 = tid >> 2, c40 = tid & 3;
    int brow = tid >> 5;
    int bcol = (tid & 31) * 4;

    uint64_t acc2[4][8];
#pragma unroll
    for (int p = 0; p < 4; p++)
#pragma unroll
        for (int j = 0; j < 8; j++) acc2[p][j] = 0ull;

    float4 aR0, aR1;
    {
        int gm0 = arow0 + row0, gm1 = gm0 + 64;
        aR0 = (gm0 < M) ? *(const float4*)(A + (size_t)gm0 * K + c40 * 4)
                        : make_float4(0.f, 0.f, 0.f, 0.f);
        aR1 = (gm1 < M) ? *(const float4*)(A + (size_t)gm1 * K + c40 * 4)
                        : make_float4(0.f, 0.f, 0.f, 0.f);
        cp_async16(&Bs[0][brow][bcol],     Bp + (size_t)brow * ldB + bn0 + bcol);
        cp_async16(&Bs[0][brow + 8][bcol], Bp + (size_t)(brow + 8) * ldB + bn0 + bcol);
        cp_commit();
        As[0][c40 * 4 + 0][row0] = aR0.x;
        As[0][c40 * 4 + 1][row0] = aR0.y;
        As[0][c40 * 4 + 2][row0] = aR0.z;
        As[0][c40 * 4 + 3][row0] = aR0.w;
        As[0][c40 * 4 + 0][row0 + 64] = aR1.x;
        As[0][c40 * 4 + 1][row0 + 64] = aR1.y;
        As[0][c40 * 4 + 2][row0 + 64] = aR1.z;
        As[0][c40 * 4 + 3][row0 + 64] = aR1.w;
    }

    int niter = K / BK;
    for (int i = 0; i < niter; i++) {
        int cur = i & 1, nxt = cur ^ 1;
        bool more = (i + 1 < niter);
        if (more) {
            int kk = (i + 1) * BK;
            int gm0 = arow0 + row0, gm1 = gm0 + 64;
            aR0 = (gm0 < M) ? *(const float4*)(A + (size_t)gm0 * K + kk + c40 * 4)
                            : make_float4(0.f, 0.f, 0.f, 0.f);
            aR1 = (gm1 < M) ? *(const float4*)(A + (size_t)gm1 * K + kk + c40 * 4)
                            : make_float4(0.f, 0.f, 0.f, 0.f);
            cp_async16(&Bs[nxt][brow][bcol],     Bp + (size_t)(kk + brow) * ldB + bn0 + bcol);
            cp_async16(&Bs[nxt][brow + 8][bcol], Bp + (size_t)(kk + brow + 8) * ldB + bn0 + bcol);
            cp_commit();
            cp_wait<1>();
        } else {
            cp_wait<0>();
        }
        __syncthreads();

#pragma unroll
        for (int k = 0; k < BK; k++) {
            float4 a0 = *(const float4*)&As[cur][k][ty * 8];
            float4 a1 = *(const float4*)&As[cur][k][ty * 8 + 4];
            uint64_t ap[4];
            ap[0] = pk2(a0.x, a0.y);
            ap[1] = pk2(a0.z, a0.w);
            ap[2] = pk2(a1.x, a1.y);
            ap[3] = pk2(a1.z, a1.w);

            float4 b0 = *(const float4*)&Bs[cur][k][tx * 8];
            float4 b1 = *(const float4*)&Bs[cur][k][tx * 8 + 4];
            float bv[8] = {b0.x, b0.y, b0.z, b0.w, b1.x, b1.y, b1.z, b1.w};
            uint64_t bp[8];
#pragma unroll
            for (int j = 0; j < 8; j++) bp[j] = pk2(bv[j], bv[j]);

#pragma unroll
            for (int p = 0; p < 4; p++)
#pragma unroll
                for (int j = 0; j < 8; j++)
                    ffma2(acc2[p][j], ap[p], bp[j]);
        }
        __syncthreads();

        if (more) {
            As[nxt][c40 * 4 + 0][row0] = aR0.x;
            As[nxt][c40 * 4 + 1][row0] = aR0.y;
            As[nxt][c40 * 4 + 2][row0] = aR0.z;
            As[nxt][c40 * 4 + 3][row0] = aR0.w;
            As[nxt][c40 * 4 + 0][row0 + 64] = aR1.x;
            As[nxt][c40 * 4 + 1][row0 + 64] = aR1.y;
            As[nxt][c40 * 4 + 2][row0 + 64] = aR1.z;
            As[nxt][c40 * 4 + 3][row0 + 64] = aR1.w;
        }
    }

    int col0 = bx * BN + tx * 8;
    float4 bs0 = *(const float4*)&bias[col0];
    float4 bs1 = *(const float4*)&bias[col0 + 4];
    const float* bb = (const float*)&bs0;
    const float* bb2 = (const float*)&bs1;
#pragma unroll
    for (int p = 0; p < 4; p++) {
        float r0[8], r1[8];
#pragma unroll
        for (int j = 0; j < 8; j++) unpk2(r0[j], r1[j], acc2[p][j]);
        int gm0 = arow0 + ty * 8 + 2 * p;
        if (gm0 < M) {
            float4 o0 = make_float4(r0[0] + bb[0], r0[1] + bb[1], r0[2] + bb[2], r0[3] + bb[3]);
            float4 o1 = make_float4(r0[4] + bb2[0], r0[5] + bb2[1], r0[6] + bb2[2], r0[7] + bb2[3]);
            *(float4*)(C + (size_t)gm0 * Ncols + col0)     = o0;
            *(float4*)(C + (size_t)gm0 * Ncols + col0 + 4) = o1;
        }
        int gm1 = gm0 + 1;
        if (gm1 < M) {
            float4 o0 = make_float4(r1[0] + bb[0], r1[1] + bb[1], r1[2] + bb[2], r1[3] + bb[3]);
            float4 o1 = make_float4(r1[4] + bb2[0], r1[5] + bb2[1], r1[6] + bb2[2], r1[7] + bb2[3]);
            *(float4*)(C + (size_t)gm1 * Ncols + col0)     = o0;
            *(float4*)(C + (size_t)gm1 * Ncols + col0 + 4) = o1;
        }
    }
}

// ---------------- CSR build ----------------
__global__ void k_zero()
{
    int i = blockIdx.x * blockDim.x + threadIdx.x;
    if (i < RN) g_cnt[i] = 0;
}

// grid (chunks, R_REL)
__global__ void k_hist(const int* __restrict__ dst)
{
    int i = blockIdx.x * blockDim.x + threadIdx.x;
    int r = blockIdx.y;
    if (i < E_EDGES)
        atomicAdd(&g_cnt[r * N_NODES + dst[(size_t)r * E_EDGES + i]], 1);
}

// ---- parallel 3-phase scan over g_cnt -> g_off/g_cur ----
// phase 1: per-block (1024 elems) scan; write local exclusive prefixes + block sum
__global__ __launch_bounds__(256) void k_scan1()
{
    __shared__ int ws[8];
    int blk = blockIdx.x, tid = threadIdx.x;
    int base = blk * 1024 + tid * 4;
    int v[4];
#pragma unroll
    for (int j = 0; j < 4; j++) {
        int i = base + j;
        v[j] = (i < RN) ? g_cnt[i] : 0;
    }
    int s = v[0] + v[1] + v[2] + v[3];
    int lane = tid & 31, w = tid >> 5;
    int ps = s;
#pragma unroll
    for (int off = 1; off < 32; off <<= 1) {
        int t = __shfl_up_sync(0xffffffffu, ps, off);
        if (lane >= off) ps += t;
    }
    if (lane == 31) ws[w] = ps;
    __syncthreads();
    if (w == 0) {
        int t = (lane < 8) ? ws[lane] : 0;
#pragma unroll
        for (int off = 1; off < 8; off <<= 1) {
            int u = __shfl_up_sync(0xffffffffu, t, off);
            if (lane >= off) t += u;
        }
        if (lane < 8) ws[lane] = t;
    }
    __syncthreads();
    int excl = ps - s + (w ? ws[w - 1] : 0);
    int run = excl;
#pragma unroll
    for (int j = 0; j < 4; j++) {
        int i = base + j;
        if (i < RN) g_pre[i] = run;
        run += v[j];
    }
    if (tid == 255) g_bsum[blk] = ws[7];
}

// phase 2: scan the 147 block sums (single block)
__global__ __launch_bounds__(256) void k_scan2()
{
    __shared__ int sm[256];
    int tid = threadIdx.x;
    int v = (tid < NCHUNK) ? g_bsum[tid] : 0;
    sm[tid] = v;
    __syncthreads();
#pragma unroll
    for (int off = 1; off < 256; off <<= 1) {
        int t = (tid >= off) ? sm[tid - off] : 0;
        __syncthreads();
        sm[tid] += t;
        __syncthreads();
    }
    if (tid < NCHUNK) g_boff[tid] = sm[tid] - v;
}

// phase 3: add block offsets, emit g_off / g_cur
__global__ __launch_bounds__(256) void k_scan3()
{
    int blk = blockIdx.x, tid = threadIdx.x;
    int add = g_boff[blk];
    int base = blk * 1024 + tid * 4;
#pragma unroll
    for (int j = 0; j < 4; j++) {
        int i = base + j;
        if (i < RN) {
            int o = g_pre[i] + add;
            g_off[i] = o;
            g_cur[i] = o;
        }
    }
    if (blk == 0 && tid == 0) g_off[RN] = RE;   // total edge count is constant
}

__global__ void k_scatter(const int* __restrict__ dst)
{
    int i = blockIdx.x * blockDim.x + threadIdx.x;
    int r = blockIdx.y;
    if (i < E_EDGES) {
        int pos = atomicAdd(&g_cur[r * N_NODES + dst[(size_t)r * E_EDGES + i]], 1);
        g_elist[pos] = i;
    }
}

// ---------------- aggregation: warp per (relation, node), SINGLE-PASS softmax ----------------
// Logits are lrelu(sign*p + q) with |.| << 88 (weight scale 0.05), so exp() without
// max-subtraction is safe and mathematically identical after the final 1/den scale.
__global__ __launch_bounds__(256) void k_agg(const int* __restrict__ src)
{
    int widx = (blockIdx.x * blockDim.x + threadIdx.x) >> 5;
    int lane = threadIdx.x & 31;
    if (widx >= RN) return;
    int r = widx / N_NODES;
    int n = widx - r * N_NODES;
    int start = g_off[widx], end = g_off[widx + 1];
    size_t obase = (size_t)n * RH + r * H_DIM;

    if (start == end) {
#pragma unroll
        for (int k = 0; k < 8; k++) g_agg[obase + lane + 32 * k] = 0.f;
        return;
    }

    float qv[4];
    {
        const float* qp = &g_pq[((size_t)r * N_NODES + n) * 8 + 4];
#pragma unroll
        for (int hh = 0; hh < 4; hh++) qv[hh] = qp[hh];
    }
    float b_n = g_sb[n] + g_Cs;
    const float* hwbase = g_hw + r * H_DIM;
    const int* srcR = src + (size_t)r * E_EDGES;
    const float* pqR = g_pq + (size_t)r * N_NODES * 8;

    float den[4], acc[8];
#pragma unroll
    for (int hh = 0; hh < 4; hh++) den[hh] = 0.f;
#pragma unroll
    for (int k = 0; k < 8; k++) acc[k] = 0.f;

    // software-pipelined: prefetch next edge's src index and pq row
    int s_cur = srcR[g_elist[start]];
    float4 pv_cur = *(const float4*)&pqR[(size_t)s_cur * 8];
    float sa_cur = g_sa[s_cur];

    for (int pos = start; pos < end; pos++) {
        int s = s_cur;
        float4 pv = pv_cur;
        float sav = sa_cur;
        if (pos + 1 < end) {
            s_cur = srcR[g_elist[pos + 1]];
            pv_cur = *(const float4*)&pqR[(size_t)s_cur * 8];
            sa_cur = g_sa[s_cur];
        }
        float sc = sav + b_n;
        float sgn = (float)((sc > 0.f) - (sc < 0.f));
        float pvv[4] = {pv.x, pv.y, pv.z, pv.w};
        float w[4];
#pragma unroll
        for (int hh = 0; hh < 4; hh++) {
            float al = fmaf(sgn, pvv[hh], qv[hh]);
            al = (al > 0.f) ? al : 0.01f * al;
            float ev = __expf(al);
            den[hh] += ev;
            w[hh] = ev * sgn;
        }
        const float* row = hwbase + (size_t)s * RH;
#pragma unroll
        for (int k = 0; k < 8; k++)
            acc[k] = fmaf(w[k >> 1], row[lane + 32 * k], acc[k]);
    }
    float inv[4];
#pragma unroll
    for (int hh = 0; hh < 4; hh++) inv[hh] = 1.f / den[hh];
#pragma unroll
    for (int k = 0; k < 8; k++)
        g_agg[obase + lane + 32 * k] = acc[k] * inv[k >> 1];
}

// ---------------- launch ----------------
extern "C" void kernel_launch(void* const* d_in, const int* in_sizes, int n_in,
                              void* d_out, int out_size)
{
    const float* h    = (const float*)d_in[0];
    const float* dW   = (const float*)d_in[1];
    const float* db   = (const float*)d_in[2];
    const float* fW   = (const float*)d_in[3];
    const float* fb   = (const float*)d_in[4];
    const float* wW   = (const float*)d_in[5];
    const float* wb   = (const float*)d_in[6];
    const float* aW   = (const float*)d_in[7];
    const float* ab   = (const float*)d_in[8];
    const float* linW = (const float*)d_in[9];
    const float* linb = (const float*)d_in[10];
    const int*   src  = (const int*)d_in[11];
    const int*   dst  = (const int*)d_in[12];
    float* out = (float*)d_out;

    float *p_hw = nullptr, *p_agg = nullptr;
    cudaGetSymbolAddress((void**)&p_hw, g_hw);
    cudaGetSymbolAddress((void**)&p_agg, g_agg);

    k_precompute<<<1, 128>>>(dW, db, fW, fb, wW, wb, aW, ab);          // 1
    k_zero<<<(RN + 255) / 256, 256>>>();                               // 2
    k_node_scalars<<<N_NODES / 4, 128>>>(h);                           // 3
    k_gemm<<<dim3(RH / BN, (N_NODES + BM - 1) / BM), 256>>>(h, wW, wb, p_hw,
                                                            N_NODES, RH, IN_F, 1); // 4
    k_hist<<<dim3((E_EDGES + 255) / 256, R_REL), 256>>>(dst);          // 5
    k_scan1<<<NCHUNK, 256>>>();                                        // 6a
    k_scan2<<<1, 256>>>();                                             // 6b
    k_scan3<<<NCHUNK, 256>>>();                                        // 6c
    k_scatter<<<dim3((E_EDGES + 255) / 256, R_REL), 256>>>(dst);       // 7
    k_agg<<<RN / 8, 256>>>(src);                                       // 8
    k_gemm<<<dim3(H_DIM / BN, (N_NODES + BM - 1) / BM), 256>>>(p_agg, linW, linb, out,
                                                               N_NODES, H_DIM, RH, 0); // 9
}

// round 10
// speedup vs baseline: 1.6922x; 1.3847x over previous
#include <cuda_runtime.h>
#include <cuda_bf16.h>
#include <cstdint>

// Problem constants
#define N_NODES 50000
#define E_EDGES 300000
#define IN_F    128
#define HFEAT   64
#define AHEADS  4
#define R_REL   3
#define H_DIM   256
#define RH      768          // R_REL * H_DIM
#define RN      (R_REL * N_NODES)
#define RE      (R_REL * E_EDGES)
#define NCHUNK  ((RN + 1023) / 1024)   // 147 scan chunks

// ---------------- device scratch (static, no allocations) ----------------
__device__ float g_hw [(size_t)N_NODES * RH];   // h @ [wW0|wW1|wW2] + bias (fp32, 153.6 MB)
__device__ float g_sa[N_NODES];
__device__ float g_sb[N_NODES];
__device__ float g_pq[(size_t)RN * 8];
__device__ float g_du[IN_F];
__device__ float g_dv[IN_F];
__device__ float g_PQ[R_REL * IN_F * 8];
__device__ float g_pqc[R_REL * 8];
__device__ float g_Cs;
__device__ int   g_cnt[RN];
__device__ int   g_off[RN + 1];
__device__ int   g_cur[RN];
__device__ int   g_elist[RE];
__device__ int   g_pre[RN];
__device__ int   g_bsum[NCHUNK];
__device__ int   g_boff[NCHUNK];
// split-bf16 operands
__device__ __nv_bfloat16 g_hh[(size_t)N_NODES * IN_F];     // h hi
__device__ __nv_bfloat16 g_hl[(size_t)N_NODES * IN_F];     // h lo
__device__ __nv_bfloat16 g_aggh[(size_t)N_NODES * RH];     // agg hi (GEMM2 A)
__device__ __nv_bfloat16 g_aggl[(size_t)N_NODES * RH];     // agg lo
// transposed+split weights: B1t[j][k] = wW[j/256][k][j%256]; B2t[c][k] = linW[k][c]
__device__ __nv_bfloat16 g_B1h[RH * IN_F];
__device__ __nv_bfloat16 g_B1l[RH * IN_F];
__device__ __nv_bfloat16 g_B2h[H_DIM * RH];
__device__ __nv_bfloat16 g_B2l[H_DIM * RH];

// ---------------- mma / ldmatrix helpers ----------------
__device__ __forceinline__ void ldsm_x4(uint32_t& r0, uint32_t& r1, uint32_t& r2, uint32_t& r3,
                                        uint32_t addr)
{
    asm volatile("ldmatrix.sync.aligned.m8n8.x4.shared.b16 {%0,%1,%2,%3}, [%4];"
                 : "=r"(r0), "=r"(r1), "=r"(r2), "=r"(r3) : "r"(addr));
}
__device__ __forceinline__ void ldsm_x2(uint32_t& r0, uint32_t& r1, uint32_t addr)
{
    asm volatile("ldmatrix.sync.aligned.m8n8.x2.shared.b16 {%0,%1}, [%2];"
                 : "=r"(r0), "=r"(r1) : "r"(addr));
}
__device__ __forceinline__ void mma16816(float* d, const uint32_t* a, const uint32_t* b)
{
    asm volatile("mma.sync.aligned.m16n8k16.row.col.f32.bf16.bf16.f32 "
                 "{%0,%1,%2,%3}, {%4,%5,%6,%7}, {%8,%9}, {%0,%1,%2,%3};"
                 : "+f"(d[0]), "+f"(d[1]), "+f"(d[2]), "+f"(d[3])
                 : "r"(a[0]), "r"(a[1]), "r"(a[2]), "r"(a[3]), "r"(b[0]), "r"(b[1]));
}
__device__ __forceinline__ void split_bf16(float x, __nv_bfloat16& hi, __nv_bfloat16& lo)
{
    hi = __float2bfloat16_rn(x);
    lo = __float2bfloat16_rn(x - __bfloat162float(hi));
}

// ---------------- tensor-core GEMM via mma.sync ----------------
// C[M,Ncols] = (Ah+Al)[M,K] @ (Bh+Bl)[Ncols,K]^T + bias, with lo*lo dropped.
// Block tile 128x128, 8 warps of 64x32. SMEM rows padded to 136 bf16.
#define SA_STR 136
#define MM_SMEM (4 * 128 * SA_STR * 2)
__global__ __launch_bounds__(256) void k_gemm_mma(const __nv_bfloat16* __restrict__ Ah,
                                                  const __nv_bfloat16* __restrict__ Al,
                                                  const __nv_bfloat16* __restrict__ Bh,
                                                  const __nv_bfloat16* __restrict__ Bl,
                                                  const float* __restrict__ bias,
                                                  float* __restrict__ C,
                                                  int M, int Ncols, int K)
{
    extern __shared__ __nv_bfloat16 smem[];
    __nv_bfloat16* sAh = smem;
    __nv_bfloat16* sAl = smem + 128 * SA_STR;
    __nv_bfloat16* sBh = smem + 2 * 128 * SA_STR;
    __nv_bfloat16* sBl = smem + 3 * 128 * SA_STR;

    int tid = threadIdx.x, wid = tid >> 5, lane = tid & 31;
    int m0 = blockIdx.y * 128, n0 = blockIdx.x * 128;
    int wm = (wid & 1) * 64, wn = (wid >> 1) * 32;

    float acc[4][4][4];
#pragma unroll
    for (int mt = 0; mt < 4; mt++)
#pragma unroll
        for (int nt = 0; nt < 4; nt++)
#pragma unroll
            for (int j = 0; j < 4; j++) acc[mt][nt][j] = 0.f;

    uint32_t uAh = (uint32_t)__cvta_generic_to_shared(sAh);
    uint32_t uAl = (uint32_t)__cvta_generic_to_shared(sAl);
    uint32_t uBh = (uint32_t)__cvta_generic_to_shared(sBh);
    uint32_t uBl = (uint32_t)__cvta_generic_to_shared(sBl);

    int r = tid >> 4, k8 = (tid & 15) * 8;
    for (int c = 0; c < K; c += 128) {
#pragma unroll
        for (int it = 0; it < 8; it++) {
            int row = r + it * 16;
            int soff = row * SA_STR + k8;
            size_t ga = (size_t)(m0 + row) * K + c + k8;
            uint4 vh = make_uint4(0, 0, 0, 0), vl = make_uint4(0, 0, 0, 0);
            if (m0 + row < M) {
                vh = *(const uint4*)(Ah + ga);
                vl = *(const uint4*)(Al + ga);
            }
            *(uint4*)(sAh + soff) = vh;
            *(uint4*)(sAl + soff) = vl;
            size_t gb = (size_t)(n0 + row) * K + c + k8;
            *(uint4*)(sBh + soff) = *(const uint4*)(Bh + gb);
            *(uint4*)(sBl + soff) = *(const uint4*)(Bl + gb);
        }
        __syncthreads();

#pragma unroll
        for (int ks = 0; ks < 8; ks++) {
            // B fragments: 4 n-tiles x {k0-7, k8-15}, hi and lo
            uint32_t bh[4][2], bl[4][2];
            int brow = wn + (lane & 7);
            int bkoff = ks * 16 + ((lane >> 3) & 1) * 8;
#pragma unroll
            for (int nt = 0; nt < 4; nt++) {
                uint32_t ba = (uint32_t)(((brow + nt * 8) * SA_STR + bkoff) * 2);
                ldsm_x2(bh[nt][0], bh[nt][1], uBh + ba);
                ldsm_x2(bl[nt][0], bl[nt][1], uBl + ba);
            }
            int arow = wm + (lane & 15);
            int akoff = ks * 16 + (lane >> 4) * 8;
#pragma unroll
            for (int mt = 0; mt < 4; mt++) {
                uint32_t aa = (uint32_t)(((arow + mt * 16) * SA_STR + akoff) * 2);
                uint32_t ah[4], al[4];
                ldsm_x4(ah[0], ah[1], ah[2], ah[3], uAh + aa);
                ldsm_x4(al[0], al[1], al[2], al[3], uAl + aa);
#pragma unroll
                for (int nt = 0; nt < 4; nt++) {
                    mma16816(acc[mt][nt], ah, bh[nt]);
                    mma16816(acc[mt][nt], ah, bl[nt]);
                    mma16816(acc[mt][nt], al, bh[nt]);
                }
            }
        }
        __syncthreads();
    }

    // epilogue: d0,d1 -> (m=lane>>2, n=(lane&3)*2); d2,d3 -> m+8
    int erow = m0 + wm + (lane >> 2);
    int ecol0 = n0 + wn + (lane & 3) * 2;
#pragma unroll
    for (int mt = 0; mt < 4; mt++) {
        int row_a = erow + mt * 16;
        int row_b = row_a + 8;
#pragma unroll
        for (int nt = 0; nt < 4; nt++) {
            int cc = ecol0 + nt * 8;
            float b0 = bias[cc], b1 = bias[cc + 1];
            if (row_a < M) {
                float2 o = make_float2(acc[mt][nt][0] + b0, acc[mt][nt][1] + b1);
                *(float2*)(C + (size_t)row_a * Ncols + cc) = o;
            }
            if (row_b < M) {
                float2 o = make_float2(acc[mt][nt][2] + b0, acc[mt][nt][3] + b1);
                *(float2*)(C + (size_t)row_b * Ncols + cc) = o;
            }
        }
    }
}

// ---------------- kernel: split h into bf16 hi/lo ----------------
__global__ void k_split_h(const float* __restrict__ h)
{
    int i = blockIdx.x * blockDim.x + threadIdx.x;
    if (i < N_NODES * IN_F) {
        __nv_bfloat16 hi, lo;
        split_bf16(h[i], hi, lo);
        g_hh[i] = hi;
        g_hl[i] = lo;
    }
}

// ---------------- kernel: transpose + split weights into bf16 hi/lo ----------------
__global__ void k_conv_w(const float* __restrict__ wW, const float* __restrict__ linW)
{
    int i = blockIdx.x * blockDim.x + threadIdx.x;
    if (i < RH * IN_F) {
        int j = i >> 7, k = i & 127;
        int r = j >> 8, cc = j & 255;
        __nv_bfloat16 hi, lo;
        split_bf16(wW[((size_t)r * IN_F + k) * H_DIM + cc], hi, lo);
        g_B1h[i] = hi;
        g_B1l[i] = lo;
    } else {
        int i2 = i - RH * IN_F;
        if (i2 < H_DIM * RH) {
            int cc = i2 / RH, k = i2 - cc * RH;
            __nv_bfloat16 hi, lo;
            split_bf16(linW[(size_t)k * H_DIM + cc], hi, lo);
            g_B2h[i2] = hi;
            g_B2l[i2] = lo;
        }
    }
}

// ---------------- kernel: tiny precompute of folded sign/attention params ----------------
__global__ void k_precompute(const float* __restrict__ dW, const float* __restrict__ db,
                             const float* __restrict__ fW, const float* __restrict__ fb,
                             const float* __restrict__ wW, const float* __restrict__ wb,
                             const float* __restrict__ aW, const float* __restrict__ ab)
{
    int i = threadIdx.x;
    if (i < IN_F) {
        float s1 = 0.f, s2 = 0.f;
        for (int j = 0; j < H_DIM; j++) {
            float u = fW[j] + fW[512 + j];
            float v = fW[256 + j] - fW[512 + j];
            float w = dW[i * H_DIM + j];
            s1 = fmaf(w, u, s1);
            s2 = fmaf(w, v, s2);
        }
        g_du[i] = s1;
        g_dv[i] = s2;
        for (int r = 0; r < R_REL; r++) {
            for (int hd = 0; hd < AHEADS; hd++) {
                float p = 0.f, q = 0.f;
                const float* wr = wW + (size_t)r * IN_F * H_DIM + (size_t)i * H_DIM + hd * HFEAT;
                const float* a1 = aW + r * 2 * HFEAT;
                const float* a2 = a1 + HFEAT;
                for (int k = 0; k < HFEAT; k++) {
                    p = fmaf(wr[k], a1[k], p);
                    q = fmaf(wr[k], a2[k], q);
                }
                g_PQ[r * (IN_F * 8) + i * 8 + hd]     = p;
                g_PQ[r * (IN_F * 8) + i * 8 + 4 + hd] = q;
            }
        }
    }
    if (i == 0) {
        float cs = fb[0];
        for (int j = 0; j < H_DIM; j++) {
            float u = fW[j] + fW[512 + j];
            float v = fW[256 + j] - fW[512 + j];
            cs = fmaf(db[j], u + v, cs);
        }
        g_Cs = cs;
        for (int r = 0; r < R_REL; r++) {
            for (int hd = 0; hd < AHEADS; hd++) {
                float pc = 0.f, qc = 0.f;
                const float* wr = wb + r * H_DIM + hd * HFEAT;
                const float* a1 = aW + r * 2 * HFEAT;
                const float* a2 = a1 + HFEAT;
                for (int k = 0; k < HFEAT; k++) {
                    pc = fmaf(wr[k], a1[k], pc);
                    qc = fmaf(wr[k], a2[k], qc);
                }
                g_pqc[r * 8 + hd]     = pc;
                g_pqc[r * 8 + 4 + hd] = qc + ab[r];
            }
        }
    }
}

// ---------------- kernel: per-node scalars (warp per node) ----------------
__global__ __launch_bounds__(128) void k_node_scalars(const float* __restrict__ h)
{
    int warp = threadIdx.x >> 5;
    int lane = threadIdx.x & 31;
    int node = blockIdx.x * 4 + warp;
    if (node >= N_NODES) return;

    float4 h4 = *(const float4*)(h + (size_t)node * IN_F + lane * 4);
    const float* hv = (const float*)&h4;

    float a = 0.f, b = 0.f;
    float pr[24];
#pragma unroll
    for (int j = 0; j < 24; j++) pr[j] = 0.f;

#pragma unroll
    for (int t = 0; t < 4; t++) {
        float x = hv[t];
        int idx = lane * 4 + t;
        a = fmaf(x, g_du[idx], a);
        b = fmaf(x, g_dv[idx], b);
#pragma unroll
        for (int r = 0; r < R_REL; r++) {
            const float4* pq4 = (const float4*)&g_PQ[r * (IN_F * 8) + idx * 8];
            float4 c0 = pq4[0], c1 = pq4[1];
            const float* c = (const float*)&c0;
            const float* d = (const float*)&c1;
#pragma unroll
            for (int j = 0; j < 4; j++) {
                pr[r * 8 + j]     = fmaf(x, c[j], pr[r * 8 + j]);
                pr[r * 8 + 4 + j] = fmaf(x, d[j], pr[r * 8 + 4 + j]);
            }
        }
    }
#pragma unroll
    for (int off = 16; off; off >>= 1) {
        a += __shfl_xor_sync(0xffffffffu, a, off);
        b += __shfl_xor_sync(0xffffffffu, b, off);
#pragma unroll
        for (int j = 0; j < 24; j++)
            pr[j] += __shfl_xor_sync(0xffffffffu, pr[j], off);
    }
    if (lane == 0) {
        g_sa[node] = a;
        g_sb[node] = b;
#pragma unroll
        for (int r = 0; r < R_REL; r++)
#pragma unroll
            for (int j = 0; j < 8; j++)
                g_pq[((size_t)r * N_NODES + node) * 8 + j] = pr[r * 8 + j] + g_pqc[r * 8 + j];
    }
}

// ---------------- CSR build ----------------
__global__ void k_zero()
{
    int i = blockIdx.x * blockDim.x + threadIdx.x;
    if (i < RN) g_cnt[i] = 0;
}

__global__ void k_hist(const int* __restrict__ dst)
{
    int i = blockIdx.x * blockDim.x + threadIdx.x;
    int r = blockIdx.y;
    if (i < E_EDGES)
        atomicAdd(&g_cnt[r * N_NODES + dst[(size_t)r * E_EDGES + i]], 1);
}

__global__ __launch_bounds__(256) void k_scan1()
{
    __shared__ int ws[8];
    int blk = blockIdx.x, tid = threadIdx.x;
    int base = blk * 1024 + tid * 4;
    int v[4];
#pragma unroll
    for (int j = 0; j < 4; j++) {
        int i = base + j;
        v[j] = (i < RN) ? g_cnt[i] : 0;
    }
    int s = v[0] + v[1] + v[2] + v[3];
    int lane = tid & 31, w = tid >> 5;
    int ps = s;
#pragma unroll
    for (int off = 1; off < 32; off <<= 1) {
        int t = __shfl_up_sync(0xffffffffu, ps, off);
        if (lane >= off) ps += t;
    }
    if (lane == 31) ws[w] = ps;
    __syncthreads();
    if (w == 0) {
        int t = (lane < 8) ? ws[lane] : 0;
#pragma unroll
        for (int off = 1; off < 8; off <<= 1) {
            int u = __shfl_up_sync(0xffffffffu, t, off);
            if (lane >= off) t += u;
        }
        if (lane < 8) ws[lane] = t;
    }
    __syncthreads();
    int excl = ps - s + (w ? ws[w - 1] : 0);
    int run = excl;
#pragma unroll
    for (int j = 0; j < 4; j++) {
        int i = base + j;
        if (i < RN) g_pre[i] = run;
        run += v[j];
    }
    if (tid == 255) g_bsum[blk] = ws[7];
}

__global__ __launch_bounds__(256) void k_scan2()
{
    __shared__ int sm[256];
    int tid = threadIdx.x;
    int v = (tid < NCHUNK) ? g_bsum[tid] : 0;
    sm[tid] = v;
    __syncthreads();
#pragma unroll
    for (int off = 1; off < 256; off <<= 1) {
        int t = (tid >= off) ? sm[tid - off] : 0;
        __syncthreads();
        sm[tid] += t;
        __syncthreads();
    }
    if (tid < NCHUNK) g_boff[tid] = sm[tid] - v;
}

__global__ __launch_bounds__(256) void k_scan3()
{
    int blk = blockIdx.x, tid = threadIdx.x;
    int add = g_boff[blk];
    int base = blk * 1024 + tid * 4;
#pragma unroll
    for (int j = 0; j < 4; j++) {
        int i = base + j;
        if (i < RN) {
            int o = g_pre[i] + add;
            g_off[i] = o;
            g_cur[i] = o;
        }
    }
    if (blk == 0 && tid == 0) g_off[RN] = RE;
}

__global__ void k_scatter(const int* __restrict__ dst)
{
    int i = blockIdx.x * blockDim.x + threadIdx.x;
    int r = blockIdx.y;
    if (i < E_EDGES) {
        int pos = atomicAdd(&g_cur[r * N_NODES + dst[(size_t)r * E_EDGES + i]], 1);
        g_elist[pos] = i;
    }
}

// ---------------- aggregation: warp per (relation, node), single-pass softmax ----------------
// Output written as split bf16 hi/lo (GEMM2 A operand).
__global__ __launch_bounds__(256) void k_agg(const int* __restrict__ src)
{
    int widx = (blockIdx.x * blockDim.x + threadIdx.x) >> 5;
    int lane = threadIdx.x & 31;
    if (widx >= RN) return;
    int r = widx / N_NODES;
    int n = widx - r * N_NODES;
    int start = g_off[widx], end = g_off[widx + 1];
    size_t obase = (size_t)n * RH + r * H_DIM;

    if (start == end) {
#pragma unroll
        for (int k = 0; k < 8; k++) {
            g_aggh[obase + lane + 32 * k] = __float2bfloat16_rn(0.f);
            g_aggl[obase + lane + 32 * k] = __float2bfloat16_rn(0.f);
        }
        return;
    }

    float qv[4];
    {
        const float* qp = &g_pq[((size_t)r * N_NODES + n) * 8 + 4];
#pragma unroll
        for (int hh = 0; hh < 4; hh++) qv[hh] = qp[hh];
    }
    float b_n = g_sb[n] + g_Cs;
    const float* hwbase = g_hw + r * H_DIM;
    const int* srcR = src + (size_t)r * E_EDGES;
    const float* pqR = g_pq + (size_t)r * N_NODES * 8;

    float den[4], acc[8];
#pragma unroll
    for (int hh = 0; hh < 4; hh++) den[hh] = 0.f;
#pragma unroll
    for (int k = 0; k < 8; k++) acc[k] = 0.f;

    int s_cur = srcR[g_elist[start]];
    float4 pv_cur = *(const float4*)&pqR[(size_t)s_cur * 8];
    float sa_cur = g_sa[s_cur];

    for (int pos = start; pos < end; pos++) {
        int s = s_cur;
        float4 pv = pv_cur;
        float sav = sa_cur;
        if (pos + 1 < end) {
            s_cur = srcR[g_elist[pos + 1]];
            pv_cur = *(const float4*)&pqR[(size_t)s_cur * 8];
            sa_cur = g_sa[s_cur];
        }
        float sc = sav + b_n;
        float sgn = (float)((sc > 0.f) - (sc < 0.f));
        float pvv[4] = {pv.x, pv.y, pv.z, pv.w};
        float w[4];
#pragma unroll
        for (int hh = 0; hh < 4; hh++) {
            float al = fmaf(sgn, pvv[hh], qv[hh]);
            al = (al > 0.f) ? al : 0.01f * al;
            float ev = __expf(al);
            den[hh] += ev;
            w[hh] = ev * sgn;
        }
        const float* row = hwbase + (size_t)s * RH;
#pragma unroll
        for (int k = 0; k < 8; k++)
            acc[k] = fmaf(w[k >> 1], row[lane + 32 * k], acc[k]);
    }
    float inv[4];
#pragma unroll
    for (int hh = 0; hh < 4; hh++) inv[hh] = 1.f / den[hh];
#pragma unroll
    for (int k = 0; k < 8; k++) {
        float v = acc[k] * inv[k >> 1];
        __nv_bfloat16 hi, lo;
        split_bf16(v, hi, lo);
        g_aggh[obase + lane + 32 * k] = hi;
        g_aggl[obase + lane + 32 * k] = lo;
    }
}

// ---------------- launch ----------------
extern "C" void kernel_launch(void* const* d_in, const int* in_sizes, int n_in,
                              void* d_out, int out_size)
{
    const float* h    = (const float*)d_in[0];
    const float* dW   = (const float*)d_in[1];
    const float* db   = (const float*)d_in[2];
    const float* fW   = (const float*)d_in[3];
    const float* fb   = (const float*)d_in[4];
    const float* wW   = (const float*)d_in[5];
    const float* wb   = (const float*)d_in[6];
    const float* aW   = (const float*)d_in[7];
    const float* ab   = (const float*)d_in[8];
    const float* linW = (const float*)d_in[9];
    const float* linb = (const float*)d_in[10];
    const int*   src  = (const int*)d_in[11];
    const int*   dst  = (const int*)d_in[12];
    float* out = (float*)d_out;

    float* p_hw = nullptr;
    __nv_bfloat16 *p_hh, *p_hl, *p_aggh, *p_aggl, *p_B1h, *p_B1l, *p_B2h, *p_B2l;
    cudaGetSymbolAddress((void**)&p_hw, g_hw);
    cudaGetSymbolAddress((void**)&p_hh, g_hh);
    cudaGetSymbolAddress((void**)&p_hl, g_hl);
    cudaGetSymbolAddress((void**)&p_aggh, g_aggh);
    cudaGetSymbolAddress((void**)&p_aggl, g_aggl);
    cudaGetSymbolAddress((void**)&p_B1h, g_B1h);
    cudaGetSymbolAddress((void**)&p_B1l, g_B1l);
    cudaGetSymbolAddress((void**)&p_B2h, g_B2h);
    cudaGetSymbolAddress((void**)&p_B2l, g_B2l);

    cudaFuncSetAttribute(k_gemm_mma, cudaFuncAttributeMaxDynamicSharedMemorySize, MM_SMEM);

    int nwelem = RH * IN_F + H_DIM * RH;
    k_precompute<<<1, 128>>>(dW, db, fW, fb, wW, wb, aW, ab);            // 1
    k_conv_w<<<(nwelem + 255) / 256, 256>>>(wW, linW);                   // 2
    k_split_h<<<(N_NODES * IN_F + 255) / 256, 256>>>(h);                 // 3
    k_zero<<<(RN + 255) / 256, 256>>>();                                 // 4
    k_gemm_mma<<<dim3(RH / 128, (N_NODES + 127) / 128), 256, MM_SMEM>>>(
        p_hh, p_hl, p_B1h, p_B1l, wb, p_hw, N_NODES, RH, IN_F);          // 5 (GEMM1)
    k_node_scalars<<<N_NODES / 4, 128>>>(h);                             // 6
    k_hist<<<dim3((E_EDGES + 255) / 256, R_REL), 256>>>(dst);            // 7
    k_scan1<<<NCHUNK, 256>>>();                                          // 8a
    k_scan2<<<1, 256>>>();                                               // 8b
    k_scan3<<<NCHUNK, 256>>>();                                          // 8c
    k_scatter<<<dim3((E_EDGES + 255) / 256, R_REL), 256>>>(dst);         // 9
    k_agg<<<RN / 8, 256>>>(src);                                         // 10
    k_gemm_mma<<<dim3(H_DIM / 128, (N_NODES + 127) / 128), 256, MM_SMEM>>>(
        p_aggh, p_aggl, p_B2h, p_B2l, linb, out, N_NODES, H_DIM, RH);    // 11 (GEMM2)
}

// round 11
// speedup vs baseline: 1.8158x; 1.0730x over previous
#include <cuda_runtime.h>
#include <cuda_bf16.h>
#include <cstdint>

// Problem constants
#define N_NODES 50000
#define E_EDGES 300000
#define IN_F    128
#define HFEAT   64
#define AHEADS  4
#define R_REL   3
#define H_DIM   256
#define RH      768          // R_REL * H_DIM
#define RN      (R_REL * N_NODES)
#define RE      (R_REL * E_EDGES)
#define NCHUNK  ((RN + 1023) / 1024)   // 147 scan chunks

// ---------------- device scratch (static, no allocations) ----------------
__device__ float g_hw [(size_t)N_NODES * RH];   // h @ [wW0|wW1|wW2] + bias (fp32)
__device__ float g_sa[N_NODES];
__device__ float g_sb[N_NODES];
__device__ float g_pq[(size_t)RN * 8];
__device__ float g_du[IN_F];
__device__ float g_dv[IN_F];
__device__ float g_PQ[R_REL * IN_F * 8];
__device__ float g_pqc[R_REL * 8];
__device__ float g_Cs;
__device__ int   g_cnt[RN];
__device__ int   g_off[RN + 1];
__device__ int   g_cur[RN];
__device__ int   g_elist[RE];
__device__ int   g_pre[RN];
__device__ int   g_bsum[NCHUNK];
__device__ int   g_boff[NCHUNK];
// split-bf16 operands
__device__ __nv_bfloat16 g_hh[(size_t)N_NODES * IN_F];
__device__ __nv_bfloat16 g_hl[(size_t)N_NODES * IN_F];
__device__ __nv_bfloat16 g_aggh[(size_t)N_NODES * RH];
__device__ __nv_bfloat16 g_aggl[(size_t)N_NODES * RH];
// transposed+split weights
__device__ __nv_bfloat16 g_B1h[RH * IN_F];
__device__ __nv_bfloat16 g_B1l[RH * IN_F];
__device__ __nv_bfloat16 g_B2h[H_DIM * RH];
__device__ __nv_bfloat16 g_B2l[H_DIM * RH];

// ---------------- helpers ----------------
__device__ __forceinline__ void ldsm_x4(uint32_t& r0, uint32_t& r1, uint32_t& r2, uint32_t& r3,
                                        uint32_t addr)
{
    asm volatile("ldmatrix.sync.aligned.m8n8.x4.shared.b16 {%0,%1,%2,%3}, [%4];"
                 : "=r"(r0), "=r"(r1), "=r"(r2), "=r"(r3) : "r"(addr));
}
__device__ __forceinline__ void ldsm_x2(uint32_t& r0, uint32_t& r1, uint32_t addr)
{
    asm volatile("ldmatrix.sync.aligned.m8n8.x2.shared.b16 {%0,%1}, [%2];"
                 : "=r"(r0), "=r"(r1) : "r"(addr));
}
__device__ __forceinline__ void mma16816(float* d, const uint32_t* a, const uint32_t* b)
{
    asm volatile("mma.sync.aligned.m16n8k16.row.col.f32.bf16.bf16.f32 "
                 "{%0,%1,%2,%3}, {%4,%5,%6,%7}, {%8,%9}, {%0,%1,%2,%3};"
                 : "+f"(d[0]), "+f"(d[1]), "+f"(d[2]), "+f"(d[3])
                 : "r"(a[0]), "r"(a[1]), "r"(a[2]), "r"(a[3]), "r"(b[0]), "r"(b[1]));
}
__device__ __forceinline__ void split_bf16(float x, __nv_bfloat16& hi, __nv_bfloat16& lo)
{
    hi = __float2bfloat16_rn(x);
    lo = __float2bfloat16_rn(x - __bfloat162float(hi));
}
__device__ __forceinline__ uint32_t pack_bf2(__nv_bfloat16 a, __nv_bfloat16 b)
{
    return (uint32_t)__bfloat16_as_ushort(a) | ((uint32_t)__bfloat16_as_ushort(b) << 16);
}
__device__ __forceinline__ void cp_async16(uint32_t smem_addr, const void* gptr)
{
    asm volatile("cp.async.cg.shared.global [%0], [%1], 16;" :: "r"(smem_addr), "l"(gptr));
}
__device__ __forceinline__ void cp_commit()
{
    asm volatile("cp.async.commit_group;");
}
template <int N>
__device__ __forceinline__ void cp_wait()
{
    asm volatile("cp.async.wait_group %0;" :: "n"(N));
}

// ---------------- tensor-core GEMM via mma.sync, cp.async double-buffered ----------------
// C[M,Ncols] = (Ah+Al)[M,K] @ (Bh+Bl)[Ncols,K]^T + bias (lo*lo dropped).
// Block tile 128x128, 8 warps of 64x32, K-chunk 64, 2 smem stages.
#define CK      64
#define SA_STR  72                      // bf16 per smem row (64 + 8 pad)
#define STG     (128 * SA_STR)          // elems per matrix per stage
#define MM_SMEM (2 * 4 * STG * 2)       // bytes = 147456
__global__ __launch_bounds__(256) void k_gemm_mma(const __nv_bfloat16* __restrict__ Ah,
                                                  const __nv_bfloat16* __restrict__ Al,
                                                  const __nv_bfloat16* __restrict__ Bh,
                                                  const __nv_bfloat16* __restrict__ Bl,
                                                  const float* __restrict__ bias,
                                                  float* __restrict__ C,
                                                  int M, int Ncols, int K)
{
    extern __shared__ __nv_bfloat16 smem[];
    uint32_t uBase = (uint32_t)__cvta_generic_to_shared(smem);

    int tid = threadIdx.x, wid = tid >> 5, lane = tid & 31;
    int m0 = blockIdx.y * 128, n0 = blockIdx.x * 128;
    int wm = (wid & 1) * 64, wn = (wid >> 1) * 32;

    float acc[4][4][4];
#pragma unroll
    for (int mt = 0; mt < 4; mt++)
#pragma unroll
        for (int nt = 0; nt < 4; nt++)
#pragma unroll
            for (int j = 0; j < 4; j++) acc[mt][nt][j] = 0.f;

    // loader mapping: idx = tid + it*256 (it 0..3); row = idx>>3, 16B chunk = idx&7
    int lrow = 0, lch = 0;
    {
        int idx0 = tid;
        lrow = idx0 >> 3; lch = idx0 & 7;   // per-it adds 32 rows
    }

    int nch = K / CK;
    // prologue: stage 0
    {
        uint32_t sb = uBase;
#pragma unroll
        for (int it = 0; it < 4; it++) {
            int row = lrow + it * 32;
            uint32_t so = (uint32_t)((row * SA_STR + lch * 8) * 2);
            int arow = m0 + row; if (arow >= M) arow = M - 1;
            size_t ga = (size_t)arow * K + lch * 8;
            size_t gb = (size_t)(n0 + row) * K + lch * 8;
            cp_async16(sb + 0 * STG * 2 + so, Ah + ga);
            cp_async16(sb + 1 * STG * 2 + so, Al + ga);
            cp_async16(sb + 2 * STG * 2 + so, Bh + gb);
            cp_async16(sb + 3 * STG * 2 + so, Bl + gb);
        }
        cp_commit();
    }

    for (int c = 0; c < nch; c++) {
        if (c + 1 < nch) {
            int kk = (c + 1) * CK;
            uint32_t sb = uBase + (uint32_t)(((c + 1) & 1) * 4 * STG * 2);
#pragma unroll
            for (int it = 0; it < 4; it++) {
                int row = lrow + it * 32;
                uint32_t so = (uint32_t)((row * SA_STR + lch * 8) * 2);
                int arow = m0 + row; if (arow >= M) arow = M - 1;
                size_t ga = (size_t)arow * K + kk + lch * 8;
                size_t gb = (size_t)(n0 + row) * K + kk + lch * 8;
                cp_async16(sb + 0 * STG * 2 + so, Ah + ga);
                cp_async16(sb + 1 * STG * 2 + so, Al + ga);
                cp_async16(sb + 2 * STG * 2 + so, Bh + gb);
                cp_async16(sb + 3 * STG * 2 + so, Bl + gb);
            }
            cp_commit();
            cp_wait<1>();
        } else {
            cp_wait<0>();
        }
        __syncthreads();

        uint32_t uAh = uBase + (uint32_t)((c & 1) * 4 * STG * 2);
        uint32_t uAl = uAh + STG * 2;
        uint32_t uBh = uAh + 2 * STG * 2;
        uint32_t uBl = uAh + 3 * STG * 2;

#pragma unroll
        for (int ks = 0; ks < 4; ks++) {
            uint32_t bh[4][2], bl[4][2];
            int brow = wn + (lane & 7);
            int bko = ks * 16 + ((lane >> 3) & 1) * 8;
#pragma unroll
            for (int nt = 0; nt < 4; nt++) {
                uint32_t ba = (uint32_t)(((brow + nt * 8) * SA_STR + bko) * 2);
                ldsm_x2(bh[nt][0], bh[nt][1], uBh + ba);
                ldsm_x2(bl[nt][0], bl[nt][1], uBl + ba);
            }
            int arow = wm + (lane & 15);
            int ako = ks * 16 + (lane >> 4) * 8;
#pragma unroll
            for (int mt = 0; mt < 4; mt++) {
                uint32_t aa = (uint32_t)(((arow + mt * 16) * SA_STR + ako) * 2);
                uint32_t ah[4], al[4];
                ldsm_x4(ah[0], ah[1], ah[2], ah[3], uAh + aa);
                ldsm_x4(al[0], al[1], al[2], al[3], uAl + aa);
#pragma unroll
                for (int nt = 0; nt < 4; nt++) {
                    mma16816(acc[mt][nt], ah, bh[nt]);
                    mma16816(acc[mt][nt], ah, bl[nt]);
                    mma16816(acc[mt][nt], al, bh[nt]);
                }
            }
        }
        __syncthreads();
    }

    // epilogue
    int erow = m0 + wm + (lane >> 2);
    int ecol0 = n0 + wn + (lane & 3) * 2;
#pragma unroll
    for (int mt = 0; mt < 4; mt++) {
        int row_a = erow + mt * 16;
        int row_b = row_a + 8;
#pragma unroll
        for (int nt = 0; nt < 4; nt++) {
            int cc = ecol0 + nt * 8;
            float b0 = bias[cc], b1 = bias[cc + 1];
            if (row_a < M) {
                float2 o = make_float2(acc[mt][nt][0] + b0, acc[mt][nt][1] + b1);
                *(float2*)(C + (size_t)row_a * Ncols + cc) = o;
            }
            if (row_b < M) {
                float2 o = make_float2(acc[mt][nt][2] + b0, acc[mt][nt][3] + b1);
                *(float2*)(C + (size_t)row_b * Ncols + cc) = o;
            }
        }
    }
}

// ---------------- kernel: split h into bf16 hi/lo ----------------
__global__ void k_split_h(const float* __restrict__ h)
{
    int i = blockIdx.x * blockDim.x + threadIdx.x;
    if (i < N_NODES * IN_F) {
        __nv_bfloat16 hi, lo;
        split_bf16(h[i], hi, lo);
        g_hh[i] = hi;
        g_hl[i] = lo;
    }
}

// ---------------- kernel: transpose + split weights into bf16 hi/lo ----------------
__global__ void k_conv_w(const float* __restrict__ wW, const float* __restrict__ linW)
{
    int i = blockIdx.x * blockDim.x + threadIdx.x;
    if (i < RH * IN_F) {
        int j = i >> 7, k = i & 127;
        int r = j >> 8, cc = j & 255;
        __nv_bfloat16 hi, lo;
        split_bf16(wW[((size_t)r * IN_F + k) * H_DIM + cc], hi, lo);
        g_B1h[i] = hi;
        g_B1l[i] = lo;
    } else {
        int i2 = i - RH * IN_F;
        if (i2 < H_DIM * RH) {
            int cc = i2 / RH, k = i2 - cc * RH;
            __nv_bfloat16 hi, lo;
            split_bf16(linW[(size_t)k * H_DIM + cc], hi, lo);
            g_B2h[i2] = hi;
            g_B2l[i2] = lo;
        }
    }
}

// ---------------- kernel: tiny precompute of folded sign/attention params ----------------
__global__ void k_precompute(const float* __restrict__ dW, const float* __restrict__ db,
                             const float* __restrict__ fW, const float* __restrict__ fb,
                             const float* __restrict__ wW, const float* __restrict__ wb,
                             const float* __restrict__ aW, const float* __restrict__ ab)
{
    int i = threadIdx.x;
    if (i < IN_F) {
        float s1 = 0.f, s2 = 0.f;
        for (int j = 0; j < H_DIM; j++) {
            float u = fW[j] + fW[512 + j];
            float v = fW[256 + j] - fW[512 + j];
            float w = dW[i * H_DIM + j];
            s1 = fmaf(w, u, s1);
            s2 = fmaf(w, v, s2);
        }
        g_du[i] = s1;
        g_dv[i] = s2;
        for (int r = 0; r < R_REL; r++) {
            for (int hd = 0; hd < AHEADS; hd++) {
                float p = 0.f, q = 0.f;
                const float* wr = wW + (size_t)r * IN_F * H_DIM + (size_t)i * H_DIM + hd * HFEAT;
                const float* a1 = aW + r * 2 * HFEAT;
                const float* a2 = a1 + HFEAT;
                for (int k = 0; k < HFEAT; k++) {
                    p = fmaf(wr[k], a1[k], p);
                    q = fmaf(wr[k], a2[k], q);
                }
                g_PQ[r * (IN_F * 8) + i * 8 + hd]     = p;
                g_PQ[r * (IN_F * 8) + i * 8 + 4 + hd] = q;
            }
        }
    }
    if (i == 0) {
        float cs = fb[0];
        for (int j = 0; j < H_DIM; j++) {
            float u = fW[j] + fW[512 + j];
            float v = fW[256 + j] - fW[512 + j];
            cs = fmaf(db[j], u + v, cs);
        }
        g_Cs = cs;
        for (int r = 0; r < R_REL; r++) {
            for (int hd = 0; hd < AHEADS; hd++) {
                float pc = 0.f, qc = 0.f;
                const float* wr = wb + r * H_DIM + hd * HFEAT;
                const float* a1 = aW + r * 2 * HFEAT;
                const float* a2 = a1 + HFEAT;
                for (int k = 0; k < HFEAT; k++) {
                    pc = fmaf(wr[k], a1[k], pc);
                    qc = fmaf(wr[k], a2[k], qc);
                }
                g_pqc[r * 8 + hd]     = pc;
                g_pqc[r * 8 + 4 + hd] = qc + ab[r];
            }
        }
    }
}

// ---------------- kernel: per-node scalars (warp per node) ----------------
__global__ __launch_bounds__(128) void k_node_scalars(const float* __restrict__ h)
{
    int warp = threadIdx.x >> 5;
    int lane = threadIdx.x & 31;
    int node = blockIdx.x * 4 + warp;
    if (node >= N_NODES) return;

    float4 h4 = *(const float4*)(h + (size_t)node * IN_F + lane * 4);
    const float* hv = (const float*)&h4;

    float a = 0.f, b = 0.f;
    float pr[24];
#pragma unroll
    for (int j = 0; j < 24; j++) pr[j] = 0.f;

#pragma unroll
    for (int t = 0; t < 4; t++) {
        float x = hv[t];
        int idx = lane * 4 + t;
        a = fmaf(x, g_du[idx], a);
        b = fmaf(x, g_dv[idx], b);
#pragma unroll
        for (int r = 0; r < R_REL; r++) {
            const float4* pq4 = (const float4*)&g_PQ[r * (IN_F * 8) + idx * 8];
            float4 c0 = pq4[0], c1 = pq4[1];
            const float* c = (const float*)&c0;
            const float* d = (const float*)&c1;
#pragma unroll
            for (int j = 0; j < 4; j++) {
                pr[r * 8 + j]     = fmaf(x, c[j], pr[r * 8 + j]);
                pr[r * 8 + 4 + j] = fmaf(x, d[j], pr[r * 8 + 4 + j]);
            }
        }
    }
#pragma unroll
    for (int off = 16; off; off >>= 1) {
        a += __shfl_xor_sync(0xffffffffu, a, off);
        b += __shfl_xor_sync(0xffffffffu, b, off);
#pragma unroll
        for (int j = 0; j < 24; j++)
            pr[j] += __shfl_xor_sync(0xffffffffu, pr[j], off);
    }
    if (lane == 0) {
        g_sa[node] = a;
        g_sb[node] = b;
#pragma unroll
        for (int r = 0; r < R_REL; r++)
#pragma unroll
            for (int j = 0; j < 8; j++)
                g_pq[((size_t)r * N_NODES + node) * 8 + j] = pr[r * 8 + j] + g_pqc[r * 8 + j];
    }
}

// ---------------- CSR build ----------------
__global__ void k_zero()
{
    int i = blockIdx.x * blockDim.x + threadIdx.x;
    if (i < RN) g_cnt[i] = 0;
}

__global__ void k_hist(const int* __restrict__ dst)
{
    int i = blockIdx.x * blockDim.x + threadIdx.x;
    int r = blockIdx.y;
    if (i < E_EDGES)
        atomicAdd(&g_cnt[r * N_NODES + dst[(size_t)r * E_EDGES + i]], 1);
}

__global__ __launch_bounds__(256) void k_scan1()
{
    __shared__ int ws[8];
    int blk = blockIdx.x, tid = threadIdx.x;
    int base = blk * 1024 + tid * 4;
    int v[4];
#pragma unroll
    for (int j = 0; j < 4; j++) {
        int i = base + j;
        v[j] = (i < RN) ? g_cnt[i] : 0;
    }
    int s = v[0] + v[1] + v[2] + v[3];
    int lane = tid & 31, w = tid >> 5;
    int ps = s;
#pragma unroll
    for (int off = 1; off < 32; off <<= 1) {
        int t = __shfl_up_sync(0xffffffffu, ps, off);
        if (lane >= off) ps += t;
    }
    if (lane == 31) ws[w] = ps;
    __syncthreads();
    if (w == 0) {
        int t = (lane < 8) ? ws[lane] : 0;
#pragma unroll
        for (int off = 1; off < 8; off <<= 1) {
            int u = __shfl_up_sync(0xffffffffu, t, off);
            if (lane >= off) t += u;
        }
        if (lane < 8) ws[lane] = t;
    }
    __syncthreads();
    int excl = ps - s + (w ? ws[w - 1] : 0);
    int run = excl;
#pragma unroll
    for (int j = 0; j < 4; j++) {
        int i = base + j;
        if (i < RN) g_pre[i] = run;
        run += v[j];
    }
    if (tid == 255) g_bsum[blk] = ws[7];
}

__global__ __launch_bounds__(256) void k_scan2()
{
    __shared__ int sm[256];
    int tid = threadIdx.x;
    int v = (tid < NCHUNK) ? g_bsum[tid] : 0;
    sm[tid] = v;
    __syncthreads();
#pragma unroll
    for (int off = 1; off < 256; off <<= 1) {
        int t = (tid >= off) ? sm[tid - off] : 0;
        __syncthreads();
        sm[tid] += t;
        __syncthreads();
    }
    if (tid < NCHUNK) g_boff[tid] = sm[tid] - v;
}

__global__ __launch_bounds__(256) void k_scan3()
{
    int blk = blockIdx.x, tid = threadIdx.x;
    int add = g_boff[blk];
    int base = blk * 1024 + tid * 4;
#pragma unroll
    for (int j = 0; j < 4; j++) {
        int i = base + j;
        if (i < RN) {
            int o = g_pre[i] + add;
            g_off[i] = o;
            g_cur[i] = o;
        }
    }
    if (blk == 0 && tid == 0) g_off[RN] = RE;
}

__global__ void k_scatter(const int* __restrict__ dst)
{
    int i = blockIdx.x * blockDim.x + threadIdx.x;
    int r = blockIdx.y;
    if (i < E_EDGES) {
        int pos = atomicAdd(&g_cur[r * N_NODES + dst[(size_t)r * E_EDGES + i]], 1);
        g_elist[pos] = i;
    }
}

// ---------------- aggregation: warp per (relation, node), single-pass softmax ----------------
// float2 gathers; output written as packed split-bf16 hi/lo.
__global__ __launch_bounds__(256) void k_agg(const int* __restrict__ src)
{
    int widx = (blockIdx.x * blockDim.x + threadIdx.x) >> 5;
    int lane = threadIdx.x & 31;
    if (widx >= RN) return;
    int r = widx / N_NODES;
    int n = widx - r * N_NODES;
    int start = g_off[widx], end = g_off[widx + 1];
    size_t obase = (size_t)n * RH + r * H_DIM;
    uint32_t* oh = (uint32_t*)(g_aggh + obase);
    uint32_t* ol = (uint32_t*)(g_aggl + obase);

    if (start == end) {
#pragma unroll
        for (int j = 0; j < 4; j++) { oh[lane + 32 * j] = 0u; ol[lane + 32 * j] = 0u; }
        return;
    }

    float qv[4];
    {
        const float* qp = &g_pq[((size_t)r * N_NODES + n) * 8 + 4];
#pragma unroll
        for (int hh = 0; hh < 4; hh++) qv[hh] = qp[hh];
    }
    float b_n = g_sb[n] + g_Cs;
    const float* hwbase = g_hw + r * H_DIM;
    const int* srcR = src + (size_t)r * E_EDGES;
    const float* pqR = g_pq + (size_t)r * N_NODES * 8;

    float den[4];
    float2 acc[4];
#pragma unroll
    for (int hh = 0; hh < 4; hh++) { den[hh] = 0.f; acc[hh] = make_float2(0.f, 0.f); }

    int s_cur = srcR[g_elist[start]];
    float4 pv_cur = *(const float4*)&pqR[(size_t)s_cur * 8];
    float sa_cur = g_sa[s_cur];

    for (int pos = start; pos < end; pos++) {
        int s = s_cur;
        float4 pv = pv_cur;
        float sav = sa_cur;
        if (pos + 1 < end) {
            s_cur = srcR[g_elist[pos + 1]];
            pv_cur = *(const float4*)&pqR[(size_t)s_cur * 8];
            sa_cur = g_sa[s_cur];
        }
        float sc = sav + b_n;
        float sgn = (float)((sc > 0.f) - (sc < 0.f));
        float pvv[4] = {pv.x, pv.y, pv.z, pv.w};
        float w[4];
#pragma unroll
        for (int hh = 0; hh < 4; hh++) {
            float al = fmaf(sgn, pvv[hh], qv[hh]);
            al = (al > 0.f) ? al : 0.01f * al;
            float ev = __expf(al);
            den[hh] += ev;
            w[hh] = ev * sgn;
        }
        const float2* row2 = (const float2*)(hwbase + (size_t)s * RH);
#pragma unroll
        for (int j = 0; j < 4; j++) {
            float2 v = row2[lane + 32 * j];
            acc[j].x = fmaf(w[j], v.x, acc[j].x);
            acc[j].y = fmaf(w[j], v.y, acc[j].y);
        }
    }
#pragma unroll
    for (int j = 0; j < 4; j++) {
        float inv = 1.f / den[j];
        float vx = acc[j].x * inv, vy = acc[j].y * inv;
        __nv_bfloat16 h0, l0, h1, l1;
        split_bf16(vx, h0, l0);
        split_bf16(vy, h1, l1);
        oh[lane + 32 * j] = pack_bf2(h0, h1);
        ol[lane + 32 * j] = pack_bf2(l0, l1);
    }
}

// ---------------- launch ----------------
extern "C" void kernel_launch(void* const* d_in, const int* in_sizes, int n_in,
                              void* d_out, int out_size)
{
    const float* h    = (const float*)d_in[0];
    const float* dW   = (const float*)d_in[1];
    const float* db   = (const float*)d_in[2];
    const float* fW   = (const float*)d_in[3];
    const float* fb   = (const float*)d_in[4];
    const float* wW   = (const float*)d_in[5];
    const float* wb   = (const float*)d_in[6];
    const float* aW   = (const float*)d_in[7];
    const float* ab   = (const float*)d_in[8];
    const float* linW = (const float*)d_in[9];
    const float* linb = (const float*)d_in[10];
    const int*   src  = (const int*)d_in[11];
    const int*   dst  = (const int*)d_in[12];
    float* out = (float*)d_out;

    float* p_hw = nullptr;
    __nv_bfloat16 *p_hh, *p_hl, *p_aggh, *p_aggl, *p_B1h, *p_B1l, *p_B2h, *p_B2l;
    cudaGetSymbolAddress((void**)&p_hw, g_hw);
    cudaGetSymbolAddress((void**)&p_hh, g_hh);
    cudaGetSymbolAddress((void**)&p_hl, g_hl);
    cudaGetSymbolAddress((void**)&p_aggh, g_aggh);
    cudaGetSymbolAddress((void**)&p_aggl, g_aggl);
    cudaGetSymbolAddress((void**)&p_B1h, g_B1h);
    cudaGetSymbolAddress((void**)&p_B1l, g_B1l);
    cudaGetSymbolAddress((void**)&p_B2h, g_B2h);
    cudaGetSymbolAddress((void**)&p_B2l, g_B2l);

    cudaFuncSetAttribute(k_gemm_mma, cudaFuncAttributeMaxDynamicSharedMemorySize, MM_SMEM);

    int nwelem = RH * IN_F + H_DIM * RH;
    k_precompute<<<1, 128>>>(dW, db, fW, fb, wW, wb, aW, ab);            // 1
    k_conv_w<<<(nwelem + 255) / 256, 256>>>(wW, linW);                   // 2
    k_split_h<<<(N_NODES * IN_F + 255) / 256, 256>>>(h);                 // 3
    k_gemm_mma<<<dim3(RH / 128, (N_NODES + 127) / 128), 256, MM_SMEM>>>(
        p_hh, p_hl, p_B1h, p_B1l, wb, p_hw, N_NODES, RH, IN_F);          // 4 (GEMM1 @ capture slot)
    k_zero<<<(RN + 255) / 256, 256>>>();                                 // 5
    k_node_scalars<<<N_NODES / 4, 128>>>(h);                             // 6
    k_hist<<<dim3((E_EDGES + 255) / 256, R_REL), 256>>>(dst);            // 7
    k_scan1<<<NCHUNK, 256>>>();                                          // 8a
    k_scan2<<<1, 256>>>();                                               // 8b
    k_scan3<<<NCHUNK, 256>>>();                                          // 8c
    k_scatter<<<dim3((E_EDGES + 255) / 256, R_REL), 256>>>(dst);         // 9
    k_agg<<<RN / 8, 256>>>(src);                                         // 10
    k_gemm_mma<<<dim3(H_DIM / 128, (N_NODES + 127) / 128), 256, MM_SMEM>>>(
        p_aggh, p_aggl, p_B2h, p_B2l, linb, out, N_NODES, H_DIM, RH);    // 11 (GEMM2)
}

// round 12
// speedup vs baseline: 1.9690x; 1.0844x over previous
#include <cuda_runtime.h>
#include <cuda_bf16.h>
#include <cstdint>

// Problem constants
#define N_NODES 50000
#define E_EDGES 300000
#define IN_F    128
#define HFEAT   64
#define AHEADS  4
#define R_REL   3
#define H_DIM   256
#define RH      768          // R_REL * H_DIM
#define RN      (R_REL * N_NODES)
#define RE      (R_REL * E_EDGES)
#define NCHUNK  ((RN + 1023) / 1024)   // 147 scan chunks

// ---------------- device scratch (static, no allocations) ----------------
__device__ float g_hw [(size_t)N_NODES * RH];   // h @ [wW0|wW1|wW2] + bias (fp32)
__device__ float g_sa[N_NODES];
__device__ float g_sb[N_NODES];
__device__ float g_pq[(size_t)RN * 8];
__device__ float g_du[IN_F];
__device__ float g_dv[IN_F];
__device__ float g_PQ[R_REL * IN_F * 8];
__device__ float g_pqc[R_REL * 8];
__device__ float g_Cs;
__device__ int   g_cnt[RN];
__device__ int   g_off[RN + 1];
__device__ int   g_cur[RN];
__device__ int   g_elist[RE];
__device__ int   g_pre[RN];
__device__ int   g_bsum[NCHUNK];
__device__ int   g_boff[NCHUNK];
// split-bf16 operands
__device__ __nv_bfloat16 g_hh[(size_t)N_NODES * IN_F];
__device__ __nv_bfloat16 g_hl[(size_t)N_NODES * IN_F];
__device__ __nv_bfloat16 g_aggh[(size_t)N_NODES * RH];
__device__ __nv_bfloat16 g_aggl[(size_t)N_NODES * RH];
// transposed+split weights
__device__ __nv_bfloat16 g_B1h[RH * IN_F];
__device__ __nv_bfloat16 g_B1l[RH * IN_F];
__device__ __nv_bfloat16 g_B2h[H_DIM * RH];
__device__ __nv_bfloat16 g_B2l[H_DIM * RH];

// ---------------- helpers ----------------
__device__ __forceinline__ void ldsm_x4(uint32_t& r0, uint32_t& r1, uint32_t& r2, uint32_t& r3,
                                        uint32_t addr)
{
    asm volatile("ldmatrix.sync.aligned.m8n8.x4.shared.b16 {%0,%1,%2,%3}, [%4];"
                 : "=r"(r0), "=r"(r1), "=r"(r2), "=r"(r3) : "r"(addr));
}
__device__ __forceinline__ void ldsm_x2(uint32_t& r0, uint32_t& r1, uint32_t addr)
{
    asm volatile("ldmatrix.sync.aligned.m8n8.x2.shared.b16 {%0,%1}, [%2];"
                 : "=r"(r0), "=r"(r1) : "r"(addr));
}
__device__ __forceinline__ void mma16816(float* d, const uint32_t* a, const uint32_t* b)
{
    asm volatile("mma.sync.aligned.m16n8k16.row.col.f32.bf16.bf16.f32 "
                 "{%0,%1,%2,%3}, {%4,%5,%6,%7}, {%8,%9}, {%0,%1,%2,%3};"
                 : "+f"(d[0]), "+f"(d[1]), "+f"(d[2]), "+f"(d[3])
                 : "r"(a[0]), "r"(a[1]), "r"(a[2]), "r"(a[3]), "r"(b[0]), "r"(b[1]));
}
__device__ __forceinline__ void split_bf16(float x, __nv_bfloat16& hi, __nv_bfloat16& lo)
{
    hi = __float2bfloat16_rn(x);
    lo = __float2bfloat16_rn(x - __bfloat162float(hi));
}
__device__ __forceinline__ uint32_t pack_bf2(__nv_bfloat16 a, __nv_bfloat16 b)
{
    return (uint32_t)__bfloat16_as_ushort(a) | ((uint32_t)__bfloat16_as_ushort(b) << 16);
}
__device__ __forceinline__ void cp_async16(uint32_t smem_addr, const void* gptr)
{
    asm volatile("cp.async.cg.shared.global [%0], [%1], 16;" :: "r"(smem_addr), "l"(gptr));
}
__device__ __forceinline__ void cp_commit()
{
    asm volatile("cp.async.commit_group;");
}
template <int N>
__device__ __forceinline__ void cp_wait()
{
    asm volatile("cp.async.wait_group %0;" :: "n"(N));
}
__device__ __forceinline__ float warp_sum(float v)
{
#pragma unroll
    for (int off = 16; off; off >>= 1) v += __shfl_xor_sync(0xffffffffu, v, off);
    return v;
}

// ---------------- tensor-core GEMM via mma.sync, cp.async 3-stage pipeline ----------------
// C[M,Ncols] = (Ah+Al)[M,K] @ (Bh+Bl)[Ncols,K]^T + bias (lo*lo dropped).
// Block tile 128x128, 8 warps of 64x32, K-chunk 64, 3 smem stages.
#define CK      64
#define SA_STR  72                      // bf16 per smem row (64 + 8 pad)
#define STG     (128 * SA_STR)          // elems per matrix per stage
#define MM_SMEM (3 * 4 * STG * 2)       // 221184 bytes
__global__ __launch_bounds__(256) void k_gemm_mma(const __nv_bfloat16* __restrict__ Ah,
                                                  const __nv_bfloat16* __restrict__ Al,
                                                  const __nv_bfloat16* __restrict__ Bh,
                                                  const __nv_bfloat16* __restrict__ Bl,
                                                  const float* __restrict__ bias,
                                                  float* __restrict__ C,
                                                  int M, int Ncols, int K)
{
    extern __shared__ __nv_bfloat16 smem[];
    uint32_t uBase = (uint32_t)__cvta_generic_to_shared(smem);

    int tid = threadIdx.x, wid = tid >> 5, lane = tid & 31;
    int m0 = blockIdx.y * 128, n0 = blockIdx.x * 128;
    int wm = (wid & 1) * 64, wn = (wid >> 1) * 32;

    float acc[4][4][4];
#pragma unroll
    for (int mt = 0; mt < 4; mt++)
#pragma unroll
        for (int nt = 0; nt < 4; nt++)
#pragma unroll
            for (int j = 0; j < 4; j++) acc[mt][nt][j] = 0.f;

    int lrow = tid >> 3, lch = tid & 7;
    int nch = K / CK;

    auto load_stage = [&](int st) {
        int kk = st * CK;
        uint32_t sb = uBase + (uint32_t)((st % 3) * 4 * STG * 2);
#pragma unroll
        for (int it = 0; it < 4; it++) {
            int row = lrow + it * 32;
            uint32_t so = (uint32_t)((row * SA_STR + lch * 8) * 2);
            int arow = m0 + row; if (arow >= M) arow = M - 1;
            size_t ga = (size_t)arow * K + kk + lch * 8;
            size_t gb = (size_t)(n0 + row) * K + kk + lch * 8;
            cp_async16(sb + 0 * STG * 2 + so, Ah + ga);
            cp_async16(sb + 1 * STG * 2 + so, Al + ga);
            cp_async16(sb + 2 * STG * 2 + so, Bh + gb);
            cp_async16(sb + 3 * STG * 2 + so, Bl + gb);
        }
        cp_commit();
    };

    load_stage(0);
    if (nch > 1) load_stage(1);

    for (int c = 0; c < nch; c++) {
        if (c + 2 < nch) {
            load_stage(c + 2);
            cp_wait<2>();
        } else if (c + 1 < nch) {
            cp_wait<1>();
        } else {
            cp_wait<0>();
        }
        __syncthreads();

        uint32_t uAh = uBase + (uint32_t)((c % 3) * 4 * STG * 2);
        uint32_t uAl = uAh + STG * 2;
        uint32_t uBh = uAh + 2 * STG * 2;
        uint32_t uBl = uAh + 3 * STG * 2;

#pragma unroll
        for (int ks = 0; ks < 4; ks++) {
            uint32_t bh[4][2], bl[4][2];
            int brow = wn + (lane & 7);
            int bko = ks * 16 + ((lane >> 3) & 1) * 8;
#pragma unroll
            for (int nt = 0; nt < 4; nt++) {
                uint32_t ba = (uint32_t)(((brow + nt * 8) * SA_STR + bko) * 2);
                ldsm_x2(bh[nt][0], bh[nt][1], uBh + ba);
                ldsm_x2(bl[nt][0], bl[nt][1], uBl + ba);
            }
            int arow = wm + (lane & 15);
            int ako = ks * 16 + (lane >> 4) * 8;
#pragma unroll
            for (int mt = 0; mt < 4; mt++) {
                uint32_t aa = (uint32_t)(((arow + mt * 16) * SA_STR + ako) * 2);
                uint32_t ah[4], al[4];
                ldsm_x4(ah[0], ah[1], ah[2], ah[3], uAh + aa);
                ldsm_x4(al[0], al[1], al[2], al[3], uAl + aa);
#pragma unroll
                for (int nt = 0; nt < 4; nt++) {
                    mma16816(acc[mt][nt], ah, bh[nt]);
                    mma16816(acc[mt][nt], ah, bl[nt]);
                    mma16816(acc[mt][nt], al, bh[nt]);
                }
            }
        }
        __syncthreads();
    }

    // epilogue
    int erow = m0 + wm + (lane >> 2);
    int ecol0 = n0 + wn + (lane & 3) * 2;
#pragma unroll
    for (int mt = 0; mt < 4; mt++) {
        int row_a = erow + mt * 16;
        int row_b = row_a + 8;
#pragma unroll
        for (int nt = 0; nt < 4; nt++) {
            int cc = ecol0 + nt * 8;
            float b0 = bias[cc], b1 = bias[cc + 1];
            if (row_a < M) {
                float2 o = make_float2(acc[mt][nt][0] + b0, acc[mt][nt][1] + b1);
                *(float2*)(C + (size_t)row_a * Ncols + cc) = o;
            }
            if (row_b < M) {
                float2 o = make_float2(acc[mt][nt][2] + b0, acc[mt][nt][3] + b1);
                *(float2*)(C + (size_t)row_b * Ncols + cc) = o;
            }
        }
    }
}

// ---------------- kernel: parallel precompute (warp per output row) ----------------
// warps 0..127: du/dv; 128..1663: PQ; 1664: Cs; 1665..1688: pqc
#define PRE_WARPS 1689
__global__ __launch_bounds__(256) void k_pre(const float* __restrict__ dW,
                                             const float* __restrict__ db,
                                             const float* __restrict__ fW,
                                             const float* __restrict__ fb,
                                             const float* __restrict__ wW,
                                             const float* __restrict__ wb,
                                             const float* __restrict__ aW,
                                             const float* __restrict__ ab)
{
    int w = blockIdx.x * 8 + (threadIdx.x >> 5);
    int lane = threadIdx.x & 31;

    if (w < 128) {
        int i = w;
        float s1 = 0.f, s2 = 0.f;
#pragma unroll
        for (int t = 0; t < 8; t++) {
            int j = lane + t * 32;
            float u = fW[j] + fW[512 + j];
            float v = fW[256 + j] - fW[512 + j];
            float x = dW[i * H_DIM + j];
            s1 = fmaf(x, u, s1);
            s2 = fmaf(x, v, s2);
        }
        s1 = warp_sum(s1);
        s2 = warp_sum(s2);
        if (lane == 0) { g_du[i] = s1; g_dv[i] = s2; }
    } else if (w < 128 + 1536) {
        int t = w - 128;
        int r = t >> 9, rem = t & 511, hd = rem >> 7, i = rem & 127;
        const float* wr = wW + ((size_t)r * IN_F + i) * H_DIM + hd * HFEAT;
        const float* a1 = aW + r * 2 * HFEAT;
        const float* a2 = a1 + HFEAT;
        float p = 0.f, q = 0.f;
#pragma unroll
        for (int tt = 0; tt < 2; tt++) {
            int k = lane + tt * 32;
            float x = wr[k];
            p = fmaf(x, a1[k], p);
            q = fmaf(x, a2[k], q);
        }
        p = warp_sum(p);
        q = warp_sum(q);
        if (lane == 0) {
            g_PQ[r * (IN_F * 8) + i * 8 + hd]     = p;
            g_PQ[r * (IN_F * 8) + i * 8 + 4 + hd] = q;
        }
    } else if (w == 1664) {
        float cs = 0.f;
#pragma unroll
        for (int t = 0; t < 8; t++) {
            int j = lane + t * 32;
            float u = fW[j] + fW[512 + j];
            float v = fW[256 + j] - fW[512 + j];
            cs = fmaf(db[j], u + v, cs);
        }
        cs = warp_sum(cs);
        if (lane == 0) g_Cs = cs + fb[0];
    } else if (w < PRE_WARPS) {
        int t = w - 1665;                 // 0..23
        int r = t >> 3, idx = t & 7;
        int hd = idx & 3;
        int isQ = idx >> 2;
        const float* wr = wb + r * H_DIM + hd * HFEAT;
        const float* av = aW + r * 2 * HFEAT + isQ * HFEAT;
        float acc = 0.f;
#pragma unroll
        for (int tt = 0; tt < 2; tt++) {
            int k = lane + tt * 32;
            acc = fmaf(wr[k], av[k], acc);
        }
        acc = warp_sum(acc);
        if (lane == 0) g_pqc[r * 8 + idx] = acc + (isQ ? ab[r] : 0.f);
    }
}

// ---------------- kernel: split h into bf16 hi/lo ----------------
__global__ void k_split_h(const float* __restrict__ h)
{
    int i = blockIdx.x * blockDim.x + threadIdx.x;
    if (i < N_NODES * IN_F) {
        __nv_bfloat16 hi, lo;
        split_bf16(h[i], hi, lo);
        g_hh[i] = hi;
        g_hl[i] = lo;
    }
}

// ---------------- kernel: transpose + split weights into bf16 hi/lo ----------------
__global__ void k_conv_w(const float* __restrict__ wW, const float* __restrict__ linW)
{
    int i = blockIdx.x * blockDim.x + threadIdx.x;
    if (i < RH * IN_F) {
        int j = i >> 7, k = i & 127;
        int r = j >> 8, cc = j & 255;
        __nv_bfloat16 hi, lo;
        split_bf16(wW[((size_t)r * IN_F + k) * H_DIM + cc], hi, lo);
        g_B1h[i] = hi;
        g_B1l[i] = lo;
    } else {
        int i2 = i - RH * IN_F;
        if (i2 < H_DIM * RH) {
            int cc = i2 / RH, k = i2 - cc * RH;
            __nv_bfloat16 hi, lo;
            split_bf16(linW[(size_t)k * H_DIM + cc], hi, lo);
            g_B2h[i2] = hi;
            g_B2l[i2] = lo;
        }
    }
}

// ---------------- kernel: per-node scalars (warp per node) ----------------
__global__ __launch_bounds__(128) void k_node_scalars(const float* __restrict__ h)
{
    int warp = threadIdx.x >> 5;
    int lane = threadIdx.x & 31;
    int node = blockIdx.x * 4 + warp;
    if (node >= N_NODES) return;

    float4 h4 = *(const float4*)(h + (size_t)node * IN_F + lane * 4);
    const float* hv = (const float*)&h4;

    float a = 0.f, b = 0.f;
    float pr[24];
#pragma unroll
    for (int j = 0; j < 24; j++) pr[j] = 0.f;

#pragma unroll
    for (int t = 0; t < 4; t++) {
        float x = hv[t];
        int idx = lane * 4 + t;
        a = fmaf(x, g_du[idx], a);
        b = fmaf(x, g_dv[idx], b);
#pragma unroll
        for (int r = 0; r < R_REL; r++) {
            const float4* pq4 = (const float4*)&g_PQ[r * (IN_F * 8) + idx * 8];
            float4 c0 = pq4[0], c1 = pq4[1];
            const float* c = (const float*)&c0;
            const float* d = (const float*)&c1;
#pragma unroll
            for (int j = 0; j < 4; j++) {
                pr[r * 8 + j]     = fmaf(x, c[j], pr[r * 8 + j]);
                pr[r * 8 + 4 + j] = fmaf(x, d[j], pr[r * 8 + 4 + j]);
            }
        }
    }
#pragma unroll
    for (int off = 16; off; off >>= 1) {
        a += __shfl_xor_sync(0xffffffffu, a, off);
        b += __shfl_xor_sync(0xffffffffu, b, off);
#pragma unroll
        for (int j = 0; j < 24; j++)
            pr[j] += __shfl_xor_sync(0xffffffffu, pr[j], off);
    }
    if (lane == 0) {
        g_sa[node] = a;
        g_sb[node] = b;
#pragma unroll
        for (int r = 0; r < R_REL; r++)
#pragma unroll
            for (int j = 0; j < 8; j++)
                g_pq[((size_t)r * N_NODES + node) * 8 + j] = pr[r * 8 + j] + g_pqc[r * 8 + j];
    }
}

// ---------------- CSR build ----------------
__global__ void k_zero()
{
    int i = blockIdx.x * blockDim.x + threadIdx.x;
    if (i < RN) g_cnt[i] = 0;
}

__global__ void k_hist(const int* __restrict__ dst)
{
    int i = blockIdx.x * blockDim.x + threadIdx.x;
    int r = blockIdx.y;
    if (i < E_EDGES)
        atomicAdd(&g_cnt[r * N_NODES + dst[(size_t)r * E_EDGES + i]], 1);
}

__global__ __launch_bounds__(256) void k_scan1()
{
    __shared__ int ws[8];
    int blk = blockIdx.x, tid = threadIdx.x;
    int base = blk * 1024 + tid * 4;
    int v[4];
#pragma unroll
    for (int j = 0; j < 4; j++) {
        int i = base + j;
        v[j] = (i < RN) ? g_cnt[i] : 0;
    }
    int s = v[0] + v[1] + v[2] + v[3];
    int lane = tid & 31, w = tid >> 5;
    int ps = s;
#pragma unroll
    for (int off = 1; off < 32; off <<= 1) {
        int t = __shfl_up_sync(0xffffffffu, ps, off);
        if (lane >= off) ps += t;
    }
    if (lane == 31) ws[w] = ps;
    __syncthreads();
    if (w == 0) {
        int t = (lane < 8) ? ws[lane] : 0;
#pragma unroll
        for (int off = 1; off < 8; off <<= 1) {
            int u = __shfl_up_sync(0xffffffffu, t, off);
            if (lane >= off) t += u;
        }
        if (lane < 8) ws[lane] = t;
    }
    __syncthreads();
    int excl = ps - s + (w ? ws[w - 1] : 0);
    int run = excl;
#pragma unroll
    for (int j = 0; j < 4; j++) {
        int i = base + j;
        if (i < RN) g_pre[i] = run;
        run += v[j];
    }
    if (tid == 255) g_bsum[blk] = ws[7];
}

__global__ __launch_bounds__(256) void k_scan2()
{
    __shared__ int sm[256];
    int tid = threadIdx.x;
    int v = (tid < NCHUNK) ? g_bsum[tid] : 0;
    sm[tid] = v;
    __syncthreads();
#pragma unroll
    for (int off = 1; off < 256; off <<= 1) {
        int t = (tid >= off) ? sm[tid - off] : 0;
        __syncthreads();
        sm[tid] += t;
        __syncthreads();
    }
    if (tid < NCHUNK) g_boff[tid] = sm[tid] - v;
}

__global__ __launch_bounds__(256) void k_scan3()
{
    int blk = blockIdx.x, tid = threadIdx.x;
    int add = g_boff[blk];
    int base = blk * 1024 + tid * 4;
#pragma unroll
    for (int j = 0; j < 4; j++) {
        int i = base + j;
        if (i < RN) {
            int o = g_pre[i] + add;
            g_off[i] = o;
            g_cur[i] = o;
        }
    }
    if (blk == 0 && tid == 0) g_off[RN] = RE;
}

__global__ void k_scatter(const int* __restrict__ dst)
{
    int i = blockIdx.x * blockDim.x + threadIdx.x;
    int r = blockIdx.y;
    if (i < E_EDGES) {
        int pos = atomicAdd(&g_cur[r * N_NODES + dst[(size_t)r * E_EDGES + i]], 1);
        g_elist[pos] = i;
    }
}

// ---------------- aggregation: warp per (relation, node), single-pass softmax ----------------
// float4 gathers (a float4 never straddles heads); packed split-bf16 output.
__global__ __launch_bounds__(256) void k_agg(const int* __restrict__ src)
{
    int widx = (blockIdx.x * blockDim.x + threadIdx.x) >> 5;
    int lane = threadIdx.x & 31;
    if (widx >= RN) return;
    int r = widx / N_NODES;
    int n = widx - r * N_NODES;
    int start = g_off[widx], end = g_off[widx + 1];
    size_t obase = (size_t)n * RH + r * H_DIM;
    uint2* oh = (uint2*)(g_aggh + obase);
    uint2* ol = (uint2*)(g_aggl + obase);

    if (start == end) {
#pragma unroll
        for (int j = 0; j < 2; j++) {
            oh[lane + 32 * j] = make_uint2(0u, 0u);
            ol[lane + 32 * j] = make_uint2(0u, 0u);
        }
        return;
    }

    float qv[4];
    {
        const float* qp = &g_pq[((size_t)r * N_NODES + n) * 8 + 4];
#pragma unroll
        for (int hh = 0; hh < 4; hh++) qv[hh] = qp[hh];
    }
    float b_n = g_sb[n] + g_Cs;
    const float* hwbase = g_hw + r * H_DIM;
    const int* srcR = src + (size_t)r * E_EDGES;
    const float* pqR = g_pq + (size_t)r * N_NODES * 8;

    float den[4];
    float4 acc[2];
#pragma unroll
    for (int hh = 0; hh < 4; hh++) den[hh] = 0.f;
    acc[0] = make_float4(0.f, 0.f, 0.f, 0.f);
    acc[1] = make_float4(0.f, 0.f, 0.f, 0.f);

    int s_cur = srcR[g_elist[start]];
    float4 pv_cur = *(const float4*)&pqR[(size_t)s_cur * 8];
    float sa_cur = g_sa[s_cur];

    for (int pos = start; pos < end; pos++) {
        int s = s_cur;
        float4 pv = pv_cur;
        float sav = sa_cur;
        if (pos + 1 < end) {
            s_cur = srcR[g_elist[pos + 1]];
            pv_cur = *(const float4*)&pqR[(size_t)s_cur * 8];
            sa_cur = g_sa[s_cur];
        }
        float sc = sav + b_n;
        float sgn = (float)((sc > 0.f) - (sc < 0.f));
        float pvv[4] = {pv.x, pv.y, pv.z, pv.w};
        float w[4];
#pragma unroll
        for (int hh = 0; hh < 4; hh++) {
            float al = fmaf(sgn, pvv[hh], qv[hh]);
            al = (al > 0.f) ? al : 0.01f * al;
            float ev = __expf(al);
            den[hh] += ev;
            w[hh] = ev * sgn;
        }
        const float4* row4 = (const float4*)(hwbase + (size_t)s * RH);
#pragma unroll
        for (int j = 0; j < 2; j++) {
            float4 v = row4[lane + 32 * j];
            float wv = w[(lane >> 4) + 2 * j];
            acc[j].x = fmaf(wv, v.x, acc[j].x);
            acc[j].y = fmaf(wv, v.y, acc[j].y);
            acc[j].z = fmaf(wv, v.z, acc[j].z);
            acc[j].w = fmaf(wv, v.w, acc[j].w);
        }
    }
#pragma unroll
    for (int j = 0; j < 2; j++) {
        float inv = 1.f / den[(lane >> 4) + 2 * j];
        float v0 = acc[j].x * inv, v1 = acc[j].y * inv;
        float v2 = acc[j].z * inv, v3 = acc[j].w * inv;
        __nv_bfloat16 h0, l0, h1, l1, h2, l2, h3, l3;
        split_bf16(v0, h0, l0);
        split_bf16(v1, h1, l1);
        split_bf16(v2, h2, l2);
        split_bf16(v3, h3, l3);
        oh[lane + 32 * j] = make_uint2(pack_bf2(h0, h1), pack_bf2(h2, h3));
        ol[lane + 32 * j] = make_uint2(pack_bf2(l0, l1), pack_bf2(l2, l3));
    }
}

// ---------------- launch ----------------
extern "C" void kernel_launch(void* const* d_in, const int* in_sizes, int n_in,
                              void* d_out, int out_size)
{
    const float* h    = (const float*)d_in[0];
    const float* dW   = (const float*)d_in[1];
    const float* db   = (const float*)d_in[2];
    const float* fW   = (const float*)d_in[3];
    const float* fb   = (const float*)d_in[4];
    const float* wW   = (const float*)d_in[5];
    const float* wb   = (const float*)d_in[6];
    const float* aW   = (const float*)d_in[7];
    const float* ab   = (const float*)d_in[8];
    const float* linW = (const float*)d_in[9];
    const float* linb = (const float*)d_in[10];
    const int*   src  = (const int*)d_in[11];
    const int*   dst  = (const int*)d_in[12];
    float* out = (float*)d_out;

    float* p_hw = nullptr;
    __nv_bfloat16 *p_hh, *p_hl, *p_aggh, *p_aggl, *p_B1h, *p_B1l, *p_B2h, *p_B2l;
    cudaGetSymbolAddress((void**)&p_hw, g_hw);
    cudaGetSymbolAddress((void**)&p_hh, g_hh);
    cudaGetSymbolAddress((void**)&p_hl, g_hl);
    cudaGetSymbolAddress((void**)&p_aggh, g_aggh);
    cudaGetSymbolAddress((void**)&p_aggl, g_aggl);
    cudaGetSymbolAddress((void**)&p_B1h, g_B1h);
    cudaGetSymbolAddress((void**)&p_B1l, g_B1l);
    cudaGetSymbolAddress((void**)&p_B2h, g_B2h);
    cudaGetSymbolAddress((void**)&p_B2l, g_B2l);

    cudaFuncSetAttribute(k_gemm_mma, cudaFuncAttributeMaxDynamicSharedMemorySize, MM_SMEM);

    int nwelem = RH * IN_F + H_DIM * RH;
    k_pre<<<(PRE_WARPS + 7) / 8, 256>>>(dW, db, fW, fb, wW, wb, aW, ab);  // 1
    k_conv_w<<<(nwelem + 255) / 256, 256>>>(wW, linW);                   // 2
    k_split_h<<<(N_NODES * IN_F + 255) / 256, 256>>>(h);                 // 3
    k_gemm_mma<<<dim3(RH / 128, (N_NODES + 127) / 128), 256, MM_SMEM>>>(
        p_hh, p_hl, p_B1h, p_B1l, wb, p_hw, N_NODES, RH, IN_F);          // 4 (GEMM1 @ capture slot)
    k_zero<<<(RN + 255) / 256, 256>>>();                                 // 5
    k_node_scalars<<<N_NODES / 4, 128>>>(h);                             // 6
    k_hist<<<dim3((E_EDGES + 255) / 256, R_REL), 256>>>(dst);            // 7
    k_scan1<<<NCHUNK, 256>>>();                                          // 8a
    k_scan2<<<1, 256>>>();                                               // 8b
    k_scan3<<<NCHUNK, 256>>>();                                          // 8c
    k_scatter<<<dim3((E_EDGES + 255) / 256, R_REL), 256>>>(dst);         // 9
    k_agg<<<RN / 8, 256>>>(src);                                         // 10
    k_gemm_mma<<<dim3(H_DIM / 128, (N_NODES + 127) / 128), 256, MM_SMEM>>>(
        p_aggh, p_aggl, p_B2h, p_B2l, linb, out, N_NODES, H_DIM, RH);    // 11 (GEMM2)
}